// round 1
// baseline (speedup 1.0000x reference)
#include <cuda_runtime.h>
#include <cuda_bf16.h>
#include <cstdint>

// ---------------- problem dims ----------------
#define BATCH 64
#define SEQ   512
#define ISZ   512
#define HSZ   1024
#define GSZ   4096           // 4*HSZ gate columns
#define KZ    1536           // ISZ + HSZ
#define KS    4608           // 3*KZ (bf16 3-term split stacked on K)
#define NB    64             // CTAs (column blocks)
#define NT    64             // gate cols per CTA (4 gates x 16 units)
#define UPB   16             // hidden units per CTA
#define KT    64             // K tile
#define NKT   (KS / KT)      // 72 K tiles

#define SMEM_STRIDE 72       // padded bf16 row stride

// ---------------- persistent scratch (static device arrays; no allocs) ----
__device__ __align__(256) __nv_bfloat16 g_Wp[(size_t)KS * GSZ];          // 37.7 MB permuted+split W
__device__ __align__(256) __nv_bfloat16 g_xhi[(size_t)BATCH * SEQ * ISZ];
__device__ __align__(256) __nv_bfloat16 g_xlo[(size_t)BATCH * SEQ * ISZ];
__device__ __align__(256) __nv_bfloat16 g_hhi[2][BATCH * HSZ];
__device__ __align__(256) __nv_bfloat16 g_hlo[2][BATCH * HSZ];
__device__ __align__(256) float         g_c[BATCH * HSZ];

// ---------------- helpers ----------------
__device__ __forceinline__ void cp_async16(void* dst, const void* src) {
    uint32_t d = (uint32_t)__cvta_generic_to_shared(dst);
    asm volatile("cp.async.cg.shared.global [%0], [%1], 16;\n" :: "r"(d), "l"(src) : "memory");
}
__device__ __forceinline__ void cp_commit() {
    asm volatile("cp.async.commit_group;\n" ::: "memory");
}

__device__ __forceinline__ float sigmoidf_(float v) {
    return 1.0f / (1.0f + expf(-v));
}

// ---------------- prep kernels (run every launch; deterministic) ----------
// Split x into bf16 hi/lo.
__global__ void prep_x(const float* __restrict__ x) {
    size_t i = (size_t)blockIdx.x * blockDim.x + threadIdx.x;
    size_t n4 = (size_t)BATCH * SEQ * ISZ / 4;
    if (i >= n4) return;
    float4 v = reinterpret_cast<const float4*>(x)[i];
    float vv[4] = {v.x, v.y, v.z, v.w};
    __nv_bfloat16 hi[4], lo[4];
#pragma unroll
    for (int j = 0; j < 4; j++) {
        hi[j] = __float2bfloat16(vv[j]);
        lo[j] = __float2bfloat16(vv[j] - __bfloat162float(hi[j]));
    }
    __nv_bfloat162* dh = reinterpret_cast<__nv_bfloat162*>(g_xhi);
    __nv_bfloat162* dl = reinterpret_cast<__nv_bfloat162*>(g_xlo);
    dh[i * 2]     = __nv_bfloat162(hi[0], hi[1]);
    dh[i * 2 + 1] = __nv_bfloat162(hi[2], hi[3]);
    dl[i * 2]     = __nv_bfloat162(lo[0], lo[1]);
    dl[i * 2 + 1] = __nv_bfloat162(lo[2], lo[3]);
}

// Permute W columns into per-CTA contiguous gate strips and split hi/lo.
// Permuted col g: blk=g/64 owns units [16*blk,16*blk+16); within block:
//   cols [0,16)=f, [16,32)=i, [32,48)=c~, [48,64)=o.
// K stacking: seg0 = W_hi (pairs z_hi), seg1 = W_hi (pairs z_lo), seg2 = W_lo (pairs z_hi).
__global__ void prep_w(const float* __restrict__ W) {
    size_t idx = (size_t)blockIdx.x * blockDim.x + threadIdx.x;
    if (idx >= (size_t)KZ * GSZ) return;
    int k = (int)(idx >> 12);
    int g = (int)(idx & (GSZ - 1));
    int blk = g >> 6, wi = g & 63;
    int gate = wi >> 4;
    int u = (blk << 4) + (wi & 15);
    float w = W[(size_t)k * GSZ + gate * HSZ + u];
    __nv_bfloat16 hi = __float2bfloat16(w);
    __nv_bfloat16 lo = __float2bfloat16(w - __bfloat162float(hi));
    g_Wp[(size_t)k * GSZ + g]              = hi;
    g_Wp[((size_t)KZ + k) * GSZ + g]       = hi;
    g_Wp[((size_t)2 * KZ + k) * GSZ + g]   = lo;
}

__global__ void prep_state() {
    int i = blockIdx.x * blockDim.x + threadIdx.x;
    if (i < 2 * BATCH * HSZ) {
        (&g_hhi[0][0])[i] = __float2bfloat16(0.0f);
        (&g_hlo[0][0])[i] = __float2bfloat16(0.0f);
    }
    if (i < BATCH * HSZ) g_c[i] = 0.0f;
}

// ---------------- per-step fused GEMM + LSTM cell kernel -------------------
// grid = 64 CTAs x 256 threads. CTA cb computes gates[64 x 64] for hidden
// units [16*cb, 16*cb+16), then does the c/h update + output write for them.
__global__ __launch_bounds__(256) void lstm_step(
    const float* __restrict__ bias,
    float* __restrict__ out,
    int t, long long out_size)
{
    __shared__ __align__(16) char smem_raw[2 * 64 * SMEM_STRIDE * 2 * 2]; // 36864 B
    __nv_bfloat16* sA = reinterpret_cast<__nv_bfloat16*>(smem_raw);       // [2][64][72]
    __nv_bfloat16* sB = sA + 2 * 64 * SMEM_STRIDE;                        // [2][64][72]
    float* sGates = reinterpret_cast<float*>(smem_raw);                   // overlay [64][64]

    const int tid  = threadIdx.x;
    const int warp = tid >> 5;
    const int lane = tid & 31;
    const int cb   = blockIdx.x;
    const int par  = t & 1;
    const int wm   = (warp >> 2) * 32;   // warp row base (2 warps in M)
    const int wn   = (warp & 3) * 16;    // warp col base (4 warps in N)

    float acc[2][2][4];
#pragma unroll
    for (int a = 0; a < 2; a++)
#pragma unroll
        for (int bq = 0; bq < 2; bq++)
#pragma unroll
            for (int cq = 0; cq < 4; cq++) acc[a][bq][cq] = 0.0f;

    // ---- tile loader (cp.async) ----
    auto load_tiles = [&](int kt, int stage) {
        const int k0  = kt * KT;
        const int seg = k0 / KZ;               // 0,1,2
        const int off = k0 - seg * KZ;
        const __nv_bfloat16* abase;
        int rstride;
        if (off < ISZ) {
            const __nv_bfloat16* base = (seg == 1) ? g_xlo : g_xhi;
            abase = base + (size_t)t * ISZ + off;      // + b * SEQ*ISZ per row
            rstride = SEQ * ISZ;
        } else {
            const __nv_bfloat16* base = (seg == 1) ? g_hlo[par] : g_hhi[par];
            abase = base + (off - ISZ);                 // + b * HSZ per row
            rstride = HSZ;
        }
        __nv_bfloat16* dA = sA + stage * 64 * SMEM_STRIDE;
        __nv_bfloat16* dB = sB + stage * 64 * SMEM_STRIDE;
        const __nv_bfloat16* bbase = g_Wp + (size_t)k0 * GSZ + cb * NT;
#pragma unroll
        for (int j = 0; j < 2; j++) {
            int ch  = tid + j * 256;           // 512 16B chunks: 64 rows x 8
            int row = ch >> 3, cc = ch & 7;
            cp_async16(dA + row * SMEM_STRIDE + cc * 8,
                       abase + (size_t)row * rstride + cc * 8);
        }
#pragma unroll
        for (int j = 0; j < 2; j++) {
            int ch  = tid + j * 256;
            int row = ch >> 3, cc = ch & 7;
            cp_async16(dB + row * SMEM_STRIDE + cc * 8,
                       bbase + (size_t)row * GSZ + cc * 8);
        }
        cp_commit();
    };

    load_tiles(0, 0);

    for (int kt = 0; kt < NKT; kt++) {
        const int stage = kt & 1;
        if (kt + 1 < NKT) {
            load_tiles(kt + 1, stage ^ 1);
            asm volatile("cp.async.wait_group 1;\n" ::: "memory");
        } else {
            asm volatile("cp.async.wait_group 0;\n" ::: "memory");
        }
        __syncthreads();

        const __nv_bfloat16* A  = sA + stage * 64 * SMEM_STRIDE;
        const __nv_bfloat16* Bm = sB + stage * 64 * SMEM_STRIDE;
#pragma unroll
        for (int kk = 0; kk < 4; kk++) {
            uint32_t a[2][4];
            uint32_t b[4];
#pragma unroll
            for (int mi = 0; mi < 2; mi++) {
                const __nv_bfloat16* p = A + (wm + mi * 16 + (lane & 15)) * SMEM_STRIDE
                                           + kk * 16 + (lane >> 4) * 8;
                uint32_t addr = (uint32_t)__cvta_generic_to_shared(p);
                asm volatile("ldmatrix.sync.aligned.m8n8.x4.shared.b16 {%0,%1,%2,%3},[%4];"
                             : "=r"(a[mi][0]), "=r"(a[mi][1]), "=r"(a[mi][2]), "=r"(a[mi][3])
                             : "r"(addr));
            }
            {
                const __nv_bfloat16* p = Bm + (kk * 16 + (lane & 15)) * SMEM_STRIDE
                                            + wn + (lane >> 4) * 8;
                uint32_t addr = (uint32_t)__cvta_generic_to_shared(p);
                asm volatile("ldmatrix.sync.aligned.m8n8.x4.trans.shared.b16 {%0,%1,%2,%3},[%4];"
                             : "=r"(b[0]), "=r"(b[1]), "=r"(b[2]), "=r"(b[3])
                             : "r"(addr));
            }
#pragma unroll
            for (int mi = 0; mi < 2; mi++)
#pragma unroll
                for (int ni = 0; ni < 2; ni++) {
                    asm volatile(
                        "mma.sync.aligned.m16n8k16.row.col.f32.bf16.bf16.f32 "
                        "{%0,%1,%2,%3},{%4,%5,%6,%7},{%8,%9},{%0,%1,%2,%3};"
                        : "+f"(acc[mi][ni][0]), "+f"(acc[mi][ni][1]),
                          "+f"(acc[mi][ni][2]), "+f"(acc[mi][ni][3])
                        : "r"(a[mi][0]), "r"(a[mi][1]), "r"(a[mi][2]), "r"(a[mi][3]),
                          "r"(b[ni * 2]), "r"(b[ni * 2 + 1]));
                }
        }
        __syncthreads();
    }

    // ---- epilogue: exchange gates via smem (overlays GEMM smem; all MMA done) ----
    {
        const int g  = lane >> 2;
        const int t4 = lane & 3;
#pragma unroll
        for (int mi = 0; mi < 2; mi++)
#pragma unroll
            for (int ni = 0; ni < 2; ni++) {
                int r = wm + mi * 16 + g;
                int c = wn + ni * 8 + t4 * 2;
                sGates[r * 64 + c]           = acc[mi][ni][0];
                sGates[r * 64 + c + 1]       = acc[mi][ni][1];
                sGates[(r + 8) * 64 + c]     = acc[mi][ni][2];
                sGates[(r + 8) * 64 + c + 1] = acc[mi][ni][3];
            }
    }
    __syncthreads();

    const int u0 = cb * UPB;
    const long long full_out = (long long)BATCH * SEQ * HSZ + 2LL * BATCH * HSZ;
#pragma unroll
    for (int j = 0; j < 4; j++) {
        int p  = tid + j * 256;        // 1024 (batch, unit) pairs
        int b  = p >> 4;
        int ui = p & 15;
        int u  = u0 + ui;
        float fg = sGates[b * 64 + ui]      + bias[u];
        float ig = sGates[b * 64 + 16 + ui] + bias[HSZ + u];
        float cg = sGates[b * 64 + 32 + ui] + bias[2 * HSZ + u];
        float og = sGates[b * 64 + 48 + ui] + bias[3 * HSZ + u];
        fg = sigmoidf_(fg);
        ig = sigmoidf_(ig);
        cg = tanhf(cg);
        og = sigmoidf_(og);
        int su = b * HSZ + u;
        float c = fg * g_c[su] + ig * cg;
        g_c[su] = c;
        float h = og * tanhf(c);
        out[((size_t)b * SEQ + t) * HSZ + u] = h;
        __nv_bfloat16 hh = __float2bfloat16(h);
        g_hhi[par ^ 1][su] = hh;
        g_hlo[par ^ 1][su] = __float2bfloat16(h - __bfloat162float(hh));
        if (t == SEQ - 1 && out_size >= full_out) {
            out[(size_t)BATCH * SEQ * HSZ + su]               = h;  // final h
            out[(size_t)BATCH * SEQ * HSZ + BATCH * HSZ + su] = c;  // final c
        }
    }
}

// ---------------- launch ----------------
extern "C" void kernel_launch(void* const* d_in, const int* in_sizes, int n_in,
                              void* d_out, int out_size) {
    const float* x = nullptr;
    const float* W = nullptr;
    const float* bias = nullptr;
    for (int i = 0; i < n_in; i++) {
        if (in_sizes[i] == BATCH * SEQ * ISZ)      x = (const float*)d_in[i];
        else if (in_sizes[i] == KZ * GSZ)          W = (const float*)d_in[i];
        else if (in_sizes[i] == GSZ)               bias = (const float*)d_in[i];
    }
    float* out = (float*)d_out;

    {
        int n4 = BATCH * SEQ * ISZ / 4;
        prep_x<<<(n4 + 255) / 256, 256>>>(x);
    }
    {
        long long n = (long long)KZ * GSZ;
        prep_w<<<(unsigned)((n + 255) / 256), 256>>>(W);
    }
    prep_state<<<(2 * BATCH * HSZ + 255) / 256, 256>>>();

    for (int t = 0; t < SEQ; t++) {
        lstm_step<<<NB, 256>>>(bias, out, t, (long long)out_size);
    }
}

// round 2
// speedup vs baseline: 2.1204x; 2.1204x over previous
#include <cuda_runtime.h>
#include <cuda_bf16.h>
#include <cstdint>

// ---------------- problem dims ----------------
#define BATCH 64
#define SEQ   512
#define ISZ   512
#define HSZ   1024
#define GSZ   4096
#define KZ    1536           // ISZ + HSZ
#define NCTA  128            // persistent CTAs, 1 per SM
#define NCOL  32             // gate columns per CTA (4 gates x 8 units)
#define UPC   8              // hidden units per CTA
#define NK16  96             // k16 tiles in K=1536
#define NKT   48             // k32 tiles per step
#define WORDS_PER_CTA (NK16 * 4 * 32 * 2)   // 24576 uint32 per W matrix per CTA

// ---------------- smem layout (bytes) ----------------
#define SM_WLO_OFF   98304
#define SM_A_OFF     196608
#define A_MAT_BYTES  5120          // 64 rows x 40 bf16 x 2B
#define A_STAGE_BYTES 10240        // hi + lo
#define SMEM_TOTAL   227328        // 192K W frags + 3 stages x 10240

// ---------------- persistent device scratch ----------------
__device__ __align__(256) unsigned      g_Wf_hi[(size_t)NCTA * WORDS_PER_CTA]; // 12.6 MB
__device__ __align__(256) unsigned      g_Wf_lo[(size_t)NCTA * WORDS_PER_CTA]; // 12.6 MB
__device__ __align__(256) __nv_bfloat16 g_xhi[(size_t)BATCH * SEQ * ISZ];
__device__ __align__(256) __nv_bfloat16 g_xlo[(size_t)BATCH * SEQ * ISZ];
__device__ __align__(256) __nv_bfloat16 g_hhi[2][BATCH * HSZ];
__device__ __align__(256) __nv_bfloat16 g_hlo[2][BATCH * HSZ];
__device__ unsigned g_bar;

// ---------------- helpers ----------------
__device__ __forceinline__ void cp_async16_s(uint32_t dst_smem, const void* src) {
    asm volatile("cp.async.cg.shared.global [%0], [%1], 16;\n"
                 :: "r"(dst_smem), "l"(src) : "memory");
}
__device__ __forceinline__ void cp_commit() {
    asm volatile("cp.async.commit_group;\n" ::: "memory");
}
__device__ __forceinline__ float sigmoidf_(float v) {
    return 1.0f / (1.0f + expf(-v));
}

#define LDSM4(R, ADDR) \
    asm volatile("ldmatrix.sync.aligned.m8n8.x4.shared.b16 {%0,%1,%2,%3},[%4];" \
                 : "=r"((R)[0]), "=r"((R)[1]), "=r"((R)[2]), "=r"((R)[3]) : "r"(ADDR))

#define MMA_BF16(ACC, A, B0, B1) \
    asm volatile("mma.sync.aligned.m16n8k16.row.col.f32.bf16.bf16.f32 " \
                 "{%0,%1,%2,%3},{%4,%5,%6,%7},{%8,%9},{%0,%1,%2,%3};" \
                 : "+f"((ACC)[0]), "+f"((ACC)[1]), "+f"((ACC)[2]), "+f"((ACC)[3]) \
                 : "r"((A)[0]), "r"((A)[1]), "r"((A)[2]), "r"((A)[3]), "r"(B0), "r"(B1))

// ---------------- prep kernels ----------------
__global__ void prep_x(const float* __restrict__ x) {
    size_t i = (size_t)blockIdx.x * blockDim.x + threadIdx.x;
    size_t n4 = (size_t)BATCH * SEQ * ISZ / 4;
    if (i >= n4) return;
    float4 v = reinterpret_cast<const float4*>(x)[i];
    float vv[4] = {v.x, v.y, v.z, v.w};
    __nv_bfloat16 hi[4], lo[4];
#pragma unroll
    for (int j = 0; j < 4; j++) {
        hi[j] = __float2bfloat16(vv[j]);
        lo[j] = __float2bfloat16(vv[j] - __bfloat162float(hi[j]));
    }
    __nv_bfloat162* dh = reinterpret_cast<__nv_bfloat162*>(g_xhi);
    __nv_bfloat162* dl = reinterpret_cast<__nv_bfloat162*>(g_xlo);
    dh[i * 2]     = __nv_bfloat162(hi[0], hi[1]);
    dh[i * 2 + 1] = __nv_bfloat162(hi[2], hi[3]);
    dl[i * 2]     = __nv_bfloat162(lo[0], lo[1]);
    dl[i * 2 + 1] = __nv_bfloat162(lo[2], lo[3]);
}

// Write W directly in m16n8k16 B-fragment order:
// word w = (((cb*96 + k16)*4 + n8)*32 + lane)*2 + q
// holds {B[k][n], B[k+1][n]} with k = k16*16 + (lane&3)*2 + q*8, n = n8*8 + lane/4.
// Column permutation: CTA cb owns units [8cb, 8cb+8); local col = gate*8 + ui.
__global__ void prep_w(const float* __restrict__ W) {
    size_t w = (size_t)blockIdx.x * blockDim.x + threadIdx.x;
    if (w >= (size_t)NCTA * WORDS_PER_CTA) return;
    size_t d = w;
    int q    = (int)(d & 1);  d >>= 1;
    int lane = (int)(d & 31); d >>= 5;
    int n8   = (int)(d & 3);  d >>= 2;
    int k16  = (int)(d % NK16);
    int cb   = (int)(d / NK16);
    int k  = k16 * 16 + (lane & 3) * 2 + q * 8;
    int nl = n8 * 8 + (lane >> 2);
    int gate = nl >> 3, ui = nl & 7;
    int col = gate * HSZ + cb * UPC + ui;
    float w0 = W[(size_t)k * GSZ + col];
    float w1 = W[(size_t)(k + 1) * GSZ + col];
    __nv_bfloat16 h0 = __float2bfloat16(w0);
    __nv_bfloat16 h1 = __float2bfloat16(w1);
    __nv_bfloat16 l0 = __float2bfloat16(w0 - __bfloat162float(h0));
    __nv_bfloat16 l1 = __float2bfloat16(w1 - __bfloat162float(h1));
    __nv_bfloat162 ph(h0, h1), pl(l0, l1);
    g_Wf_hi[w] = *reinterpret_cast<unsigned*>(&ph);
    g_Wf_lo[w] = *reinterpret_cast<unsigned*>(&pl);
}

__global__ void prep_state() {
    int i = blockIdx.x * blockDim.x + threadIdx.x;
    int n = 2 * BATCH * HSZ;
    if (i < n) {
        (&g_hhi[0][0])[i] = __float2bfloat16(0.0f);
        (&g_hlo[0][0])[i] = __float2bfloat16(0.0f);
    }
    if (i == 0) g_bar = 0u;
}

// ---------------- persistent LSTM kernel ----------------
// 128 CTAs x 256 threads, W-fragments resident in SMEM, 512 steps with
// software grid barrier. CTA cb owns hidden units [8cb, 8cb+8).
__global__ void __launch_bounds__(256, 1) lstm_persist(
    const float* __restrict__ bias,
    float* __restrict__ out,
    int write_final)
{
    extern __shared__ char smem[];
    float* sG = reinterpret_cast<float*>(smem + SM_A_OFF);   // overlays A stage 0

    const int tid  = threadIdx.x;
    const int warp = tid >> 5;
    const int lane = tid & 31;
    const int cb   = blockIdx.x;
    const int mw   = warp >> 1;          // 4 M-warps
    const int nw   = warp & 1;           // 2 N-warps
    const int wm   = mw * 16;

    // ---- resident W fragment preload (once) ----
    {
        const uint4* sh = reinterpret_cast<const uint4*>(g_Wf_hi + (size_t)cb * WORDS_PER_CTA);
        const uint4* sl = reinterpret_cast<const uint4*>(g_Wf_lo + (size_t)cb * WORDS_PER_CTA);
        uint4* dh = reinterpret_cast<uint4*>(smem);
        uint4* dl = reinterpret_cast<uint4*>(smem + SM_WLO_OFF);
        for (int i = tid; i < WORDS_PER_CTA / 4; i += 256) { dh[i] = sh[i]; dl[i] = sl[i]; }
    }

    // ---- per-thread cell state + bias (CTA owns same units all steps) ----
    const int ui = tid & 7;
    const int u  = cb * UPC + ui;
    const float bf = bias[u];
    const float bi = bias[HSZ + u];
    const float bc = bias[2 * HSZ + u];
    const float bo = bias[3 * HSZ + u];
    const int b0r = tid >> 3;        // batches 0..31
    const int b1r = b0r + 32;        // batches 32..63
    float c0 = 0.0f, c1 = 0.0f;

    const uint32_t sW_u = (uint32_t)__cvta_generic_to_shared(smem);
    const uint32_t sA_u = sW_u + SM_A_OFF;
    const uint32_t arow = (uint32_t)((wm + (lane & 15)) * 80 + (lane >> 4) * 16);
    const int lrow = tid >> 2, lcc = tid & 3;

    __syncthreads();

    for (int t = 0; t < SEQ; t++) {
        const int rb = t & 1, wb = rb ^ 1;
        float acc[2][4] = {{0.f,0.f,0.f,0.f},{0.f,0.f,0.f,0.f}};

        auto load_tile = [&](int kt, int stage) {
            const int k0 = kt * 32;
            const __nv_bfloat16 *ph, *pl;
            size_t rs;
            if (k0 < ISZ) {
                ph = g_xhi + (size_t)t * ISZ + k0;
                pl = g_xlo + (size_t)t * ISZ + k0;
                rs = (size_t)SEQ * ISZ;
            } else {
                ph = g_hhi[rb] + (k0 - ISZ);
                pl = g_hlo[rb] + (k0 - ISZ);
                rs = HSZ;
            }
            uint32_t dst = sA_u + stage * A_STAGE_BYTES + lrow * 80 + lcc * 16;
            cp_async16_s(dst,               ph + rs * lrow + lcc * 8);
            cp_async16_s(dst + A_MAT_BYTES, pl + rs * lrow + lcc * 8);
            cp_commit();
        };

        load_tile(0, 0);
        load_tile(1, 1);

        for (int kt0 = 0; kt0 < NKT; kt0 += 6) {
#pragma unroll
            for (int j = 0; j < 6; j++) {
                const int kt = kt0 + j;
                if (kt == NKT - 1) { asm volatile("cp.async.wait_group 0;\n" ::: "memory"); }
                else               { asm volatile("cp.async.wait_group 1;\n" ::: "memory"); }
                __syncthreads();
                if (kt + 2 < NKT) load_tile(kt + 2, (j + 2) % 3);

                const uint32_t Ab = sA_u + (j % 3) * A_STAGE_BYTES + arow;
#pragma unroll
                for (int sub = 0; sub < 2; sub++) {
                    uint32_t ah[4], al[4];
                    LDSM4(ah, Ab + sub * 32);
                    LDSM4(al, Ab + A_MAT_BYTES + sub * 32);
                    const int K16 = kt * 2 + sub;
#pragma unroll
                    for (int ni = 0; ni < 2; ni++) {
                        const int n8 = nw * 2 + ni;
                        const uint32_t boff = (uint32_t)((K16 * 4 + n8) * 256 + lane * 8);
                        uint32_t bh0, bh1, bl0, bl1;
                        asm volatile("ld.shared.v2.u32 {%0,%1},[%2];"
                                     : "=r"(bh0), "=r"(bh1) : "r"(sW_u + boff));
                        asm volatile("ld.shared.v2.u32 {%0,%1},[%2];"
                                     : "=r"(bl0), "=r"(bl1) : "r"(sW_u + SM_WLO_OFF + boff));
                        MMA_BF16(acc[ni], ah, bh0, bh1);
                        MMA_BF16(acc[ni], al, bh0, bh1);
                        MMA_BF16(acc[ni], ah, bl0, bl1);
                    }
                }
            }
        }

        // ---- epilogue: exchange gate tiles via smem (overlays A staging) ----
        __syncthreads();
        {
            const int g = lane >> 2, t4 = lane & 3;
#pragma unroll
            for (int ni = 0; ni < 2; ni++) {
                const int r = wm + g;
                const int c = nw * 16 + ni * 8 + t4 * 2;
                sG[r * 32 + c]            = acc[ni][0];
                sG[r * 32 + c + 1]        = acc[ni][1];
                sG[(r + 8) * 32 + c]      = acc[ni][2];
                sG[(r + 8) * 32 + c + 1]  = acc[ni][3];
            }
        }
        __syncthreads();

        // ---- cell update: each thread owns (b0r,ui) and (b1r,ui) ----
#pragma unroll
        for (int j = 0; j < 2; j++) {
            const int b = j ? b1r : b0r;
            float& c = j ? c1 : c0;
            float fg = sigmoidf_(sG[b * 32 + ui]       + bf);
            float ig = sigmoidf_(sG[b * 32 + 8 + ui]   + bi);
            float cg = tanhf    (sG[b * 32 + 16 + ui]  + bc);
            float og = sigmoidf_(sG[b * 32 + 24 + ui]  + bo);
            c = fg * c + ig * cg;
            float h = og * tanhf(c);
            out[((size_t)b * SEQ + t) * HSZ + u] = h;
            __nv_bfloat16 hh = __float2bfloat16(h);
            g_hhi[wb][b * HSZ + u] = hh;
            g_hlo[wb][b * HSZ + u] = __float2bfloat16(h - __bfloat162float(hh));
            if (t == SEQ - 1 && write_final) {
                out[(size_t)BATCH * SEQ * HSZ + b * HSZ + u]               = h;
                out[(size_t)BATCH * SEQ * HSZ + BATCH * HSZ + b * HSZ + u] = c;
            }
        }

        // ---- software grid barrier ----
        __syncthreads();
        if (tid == 0) {
            __threadfence();
            atomicAdd(&g_bar, 1u);
            const unsigned tgt = (unsigned)NCTA * (unsigned)(t + 1);
            unsigned v;
            do {
                asm volatile("ld.acquire.gpu.u32 %0,[%1];" : "=r"(v) : "l"(&g_bar) : "memory");
            } while (v < tgt);
            __threadfence();
        }
        __syncthreads();
    }
}

// ---------------- launch ----------------
extern "C" void kernel_launch(void* const* d_in, const int* in_sizes, int n_in,
                              void* d_out, int out_size) {
    const float* x = nullptr;
    const float* W = nullptr;
    const float* bias = nullptr;
    for (int i = 0; i < n_in; i++) {
        if (in_sizes[i] == BATCH * SEQ * ISZ)      x = (const float*)d_in[i];
        else if (in_sizes[i] == KZ * GSZ)          W = (const float*)d_in[i];
        else if (in_sizes[i] == GSZ)               bias = (const float*)d_in[i];
    }
    float* out = (float*)d_out;
    const long long full = (long long)BATCH * SEQ * HSZ + 2LL * BATCH * HSZ;
    const int write_final = (out_size >= full) ? 1 : 0;

    cudaFuncSetAttribute(lstm_persist, cudaFuncAttributeMaxDynamicSharedMemorySize, SMEM_TOTAL);

    {
        int n4 = BATCH * SEQ * ISZ / 4;
        prep_x<<<(n4 + 255) / 256, 256>>>(x);
    }
    {
        long long n = (long long)NCTA * WORDS_PER_CTA;
        prep_w<<<(unsigned)((n + 255) / 256), 256>>>(W);
    }
    prep_state<<<(2 * BATCH * HSZ + 255) / 256, 256>>>();

    lstm_persist<<<NCTA, 256, SMEM_TOTAL>>>(bias, out, write_final);
}

// round 3
// speedup vs baseline: 2.1336x; 1.0062x over previous
#include <cuda_runtime.h>
#include <cuda_bf16.h>
#include <cstdint>

// ---------------- problem dims ----------------
#define BATCH 64
#define SEQ   512
#define ISZ   512
#define HSZ   1024
#define GSZ   4096
#define KZ    1536           // ISZ + HSZ
#define NCTA  128            // persistent CTAs, 1 per SM
#define NCOL  32             // gate columns per CTA (4 gates x 8 units)
#define UPC   8              // hidden units per CTA
#define NK16  96             // k16 tiles in K=1536
#define NKT   48             // k32 tiles per step
#define WORDS_PER_CTA (NK16 * 4 * 32 * 2)   // 24576 uint32 per W matrix per CTA

// ---------------- smem layout (bytes) ----------------
#define SM_WLO_OFF   98304
#define SM_A_OFF     196608
#define A_MAT_BYTES  5120          // 64 rows x 40 bf16 x 2B
#define A_STAGE_BYTES 10240        // hi + lo
#define SMEM_TOTAL   227328        // 192K W frags + 3 stages x 10240

// ---------------- persistent device scratch ----------------
__device__ __align__(256) unsigned      g_Wf_hi[(size_t)NCTA * WORDS_PER_CTA]; // 12.6 MB
__device__ __align__(256) unsigned      g_Wf_lo[(size_t)NCTA * WORDS_PER_CTA]; // 12.6 MB
__device__ __align__(256) __nv_bfloat16 g_xhi[(size_t)BATCH * SEQ * ISZ];
__device__ __align__(256) __nv_bfloat16 g_xlo[(size_t)BATCH * SEQ * ISZ];
__device__ __align__(256) __nv_bfloat16 g_hhi[2][BATCH * HSZ];
__device__ __align__(256) __nv_bfloat16 g_hlo[2][BATCH * HSZ];
__device__ unsigned g_bar;

// ---------------- helpers ----------------
__device__ __forceinline__ void cp_async16_s(uint32_t dst_smem, const void* src) {
    asm volatile("cp.async.cg.shared.global [%0], [%1], 16;\n"
                 :: "r"(dst_smem), "l"(src) : "memory");
}
__device__ __forceinline__ void cp_commit() {
    asm volatile("cp.async.commit_group;\n" ::: "memory");
}
__device__ __forceinline__ float sigmoidf_(float v) {
    return 1.0f / (1.0f + expf(-v));
}

#define LDSM4(R, ADDR) \
    asm volatile("ldmatrix.sync.aligned.m8n8.x4.shared.b16 {%0,%1,%2,%3},[%4];" \
                 : "=r"((R)[0]), "=r"((R)[1]), "=r"((R)[2]), "=r"((R)[3]) : "r"(ADDR))

#define MMA_BF16(ACC, A, B0, B1) \
    asm volatile("mma.sync.aligned.m16n8k16.row.col.f32.bf16.bf16.f32 " \
                 "{%0,%1,%2,%3},{%4,%5,%6,%7},{%8,%9},{%0,%1,%2,%3};" \
                 : "+f"((ACC)[0]), "+f"((ACC)[1]), "+f"((ACC)[2]), "+f"((ACC)[3]) \
                 : "r"((A)[0]), "r"((A)[1]), "r"((A)[2]), "r"((A)[3]), "r"(B0), "r"(B1))

// ---------------- prep kernels ----------------
__global__ void prep_x(const float* __restrict__ x) {
    size_t i = (size_t)blockIdx.x * blockDim.x + threadIdx.x;
    size_t n4 = (size_t)BATCH * SEQ * ISZ / 4;
    if (i >= n4) return;
    float4 v = reinterpret_cast<const float4*>(x)[i];
    float vv[4] = {v.x, v.y, v.z, v.w};
    __nv_bfloat16 hi[4], lo[4];
#pragma unroll
    for (int j = 0; j < 4; j++) {
        hi[j] = __float2bfloat16(vv[j]);
        lo[j] = __float2bfloat16(vv[j] - __bfloat162float(hi[j]));
    }
    __nv_bfloat162* dh = reinterpret_cast<__nv_bfloat162*>(g_xhi);
    __nv_bfloat162* dl = reinterpret_cast<__nv_bfloat162*>(g_xlo);
    dh[i * 2]     = __nv_bfloat162(hi[0], hi[1]);
    dh[i * 2 + 1] = __nv_bfloat162(hi[2], hi[3]);
    dl[i * 2]     = __nv_bfloat162(lo[0], lo[1]);
    dl[i * 2 + 1] = __nv_bfloat162(lo[2], lo[3]);
}

// Write W directly in m16n8k16 B-fragment order:
// word w = (((cb*96 + k16)*4 + n8)*32 + lane)*2 + q
// holds {B[k][n], B[k+1][n]} with k = k16*16 + (lane&3)*2 + q*8, n = n8*8 + lane/4.
// Column permutation: CTA cb owns units [8cb, 8cb+8); local col = gate*8 + ui.
__global__ void prep_w(const float* __restrict__ W) {
    size_t w = (size_t)blockIdx.x * blockDim.x + threadIdx.x;
    if (w >= (size_t)NCTA * WORDS_PER_CTA) return;
    size_t d = w;
    int q    = (int)(d & 1);  d >>= 1;
    int lane = (int)(d & 31); d >>= 5;
    int n8   = (int)(d & 3);  d >>= 2;
    int k16  = (int)(d % NK16);
    int cb   = (int)(d / NK16);
    int k  = k16 * 16 + (lane & 3) * 2 + q * 8;
    int nl = n8 * 8 + (lane >> 2);
    int gate = nl >> 3, ui = nl & 7;
    int col = gate * HSZ + cb * UPC + ui;
    float w0 = W[(size_t)k * GSZ + col];
    float w1 = W[(size_t)(k + 1) * GSZ + col];
    __nv_bfloat16 h0 = __float2bfloat16(w0);
    __nv_bfloat16 h1 = __float2bfloat16(w1);
    __nv_bfloat16 l0 = __float2bfloat16(w0 - __bfloat162float(h0));
    __nv_bfloat16 l1 = __float2bfloat16(w1 - __bfloat162float(h1));
    __nv_bfloat162 ph(h0, h1), pl(l0, l1);
    g_Wf_hi[w] = *reinterpret_cast<unsigned*>(&ph);
    g_Wf_lo[w] = *reinterpret_cast<unsigned*>(&pl);
}

__global__ void prep_state() {
    int i = blockIdx.x * blockDim.x + threadIdx.x;
    int n = 2 * BATCH * HSZ;
    if (i < n) {
        (&g_hhi[0][0])[i] = __float2bfloat16(0.0f);
        (&g_hlo[0][0])[i] = __float2bfloat16(0.0f);
    }
    if (i == 0) g_bar = 0u;
}

// ---------------- persistent LSTM kernel ----------------
// 128 CTAs x 256 threads, W-fragments resident in SMEM, 512 steps with
// software grid barrier. CTA cb owns hidden units [8cb, 8cb+8).
__global__ void __launch_bounds__(256, 1) lstm_persist(
    const float* __restrict__ bias,
    float* __restrict__ out,
    int write_final)
{
    extern __shared__ char smem[];
    float* sG = reinterpret_cast<float*>(smem + SM_A_OFF);   // overlays A stage 0

    const int tid  = threadIdx.x;
    const int warp = tid >> 5;
    const int lane = tid & 31;
    const int cb   = blockIdx.x;
    const int mw   = warp >> 1;          // 4 M-warps
    const int nw   = warp & 1;           // 2 N-warps
    const int wm   = mw * 16;

    // ---- resident W fragment preload (once) ----
    {
        const uint4* sh = reinterpret_cast<const uint4*>(g_Wf_hi + (size_t)cb * WORDS_PER_CTA);
        const uint4* sl = reinterpret_cast<const uint4*>(g_Wf_lo + (size_t)cb * WORDS_PER_CTA);
        uint4* dh = reinterpret_cast<uint4*>(smem);
        uint4* dl = reinterpret_cast<uint4*>(smem + SM_WLO_OFF);
        for (int i = tid; i < WORDS_PER_CTA / 4; i += 256) { dh[i] = sh[i]; dl[i] = sl[i]; }
    }

    // ---- per-thread cell state + bias (CTA owns same units all steps) ----
    const int ui = tid & 7;
    const int u  = cb * UPC + ui;
    const float bf = bias[u];
    const float bi = bias[HSZ + u];
    const float bc = bias[2 * HSZ + u];
    const float bo = bias[3 * HSZ + u];
    const int b0r = tid >> 3;        // batches 0..31
    const int b1r = b0r + 32;        // batches 32..63
    float c0 = 0.0f, c1 = 0.0f;

    const uint32_t sW_u = (uint32_t)__cvta_generic_to_shared(smem);
    const uint32_t sA_u = sW_u + SM_A_OFF;
    const uint32_t arow = (uint32_t)((wm + (lane & 15)) * 80 + (lane >> 4) * 16);
    const int lrow = tid >> 2, lcc = tid & 3;

    __syncthreads();

    for (int t = 0; t < SEQ; t++) {
        const int rb = t & 1, wb = rb ^ 1;
        float acc[2][4] = {{0.f,0.f,0.f,0.f},{0.f,0.f,0.f,0.f}};

        auto load_tile = [&](int kt, int stage) {
            const int k0 = kt * 32;
            const __nv_bfloat16 *ph, *pl;
            size_t rs;
            if (k0 < ISZ) {
                ph = g_xhi + (size_t)t * ISZ + k0;
                pl = g_xlo + (size_t)t * ISZ + k0;
                rs = (size_t)SEQ * ISZ;
            } else {
                ph = g_hhi[rb] + (k0 - ISZ);
                pl = g_hlo[rb] + (k0 - ISZ);
                rs = HSZ;
            }
            uint32_t dst = sA_u + stage * A_STAGE_BYTES + lrow * 80 + lcc * 16;
            cp_async16_s(dst,               ph + rs * lrow + lcc * 8);
            cp_async16_s(dst + A_MAT_BYTES, pl + rs * lrow + lcc * 8);
            cp_commit();
        };

        load_tile(0, 0);
        load_tile(1, 1);

        for (int kt0 = 0; kt0 < NKT; kt0 += 6) {
#pragma unroll
            for (int j = 0; j < 6; j++) {
                const int kt = kt0 + j;
                if (kt == NKT - 1) { asm volatile("cp.async.wait_group 0;\n" ::: "memory"); }
                else               { asm volatile("cp.async.wait_group 1;\n" ::: "memory"); }
                __syncthreads();
                if (kt + 2 < NKT) load_tile(kt + 2, (j + 2) % 3);

                const uint32_t Ab = sA_u + (j % 3) * A_STAGE_BYTES + arow;
#pragma unroll
                for (int sub = 0; sub < 2; sub++) {
                    uint32_t ah[4], al[4];
                    LDSM4(ah, Ab + sub * 32);
                    LDSM4(al, Ab + A_MAT_BYTES + sub * 32);
                    const int K16 = kt * 2 + sub;
#pragma unroll
                    for (int ni = 0; ni < 2; ni++) {
                        const int n8 = nw * 2 + ni;
                        const uint32_t boff = (uint32_t)((K16 * 4 + n8) * 256 + lane * 8);
                        uint32_t bh0, bh1, bl0, bl1;
                        asm volatile("ld.shared.v2.u32 {%0,%1},[%2];"
                                     : "=r"(bh0), "=r"(bh1) : "r"(sW_u + boff));
                        asm volatile("ld.shared.v2.u32 {%0,%1},[%2];"
                                     : "=r"(bl0), "=r"(bl1) : "r"(sW_u + SM_WLO_OFF + boff));
                        MMA_BF16(acc[ni], ah, bh0, bh1);
                        MMA_BF16(acc[ni], al, bh0, bh1);
                        MMA_BF16(acc[ni], ah, bl0, bl1);
                    }
                }
            }
        }

        // ---- epilogue: exchange gate tiles via smem (overlays A staging) ----
        __syncthreads();
        {
            const int g = lane >> 2, t4 = lane & 3;
#pragma unroll
            for (int ni = 0; ni < 2; ni++) {
                const int r = wm + g;
                const int c = nw * 16 + ni * 8 + t4 * 2;
                sG[r * 32 + c]            = acc[ni][0];
                sG[r * 32 + c + 1]        = acc[ni][1];
                sG[(r + 8) * 32 + c]      = acc[ni][2];
                sG[(r + 8) * 32 + c + 1]  = acc[ni][3];
            }
        }
        __syncthreads();

        // ---- cell update: each thread owns (b0r,ui) and (b1r,ui) ----
#pragma unroll
        for (int j = 0; j < 2; j++) {
            const int b = j ? b1r : b0r;
            float& c = j ? c1 : c0;
            float fg = sigmoidf_(sG[b * 32 + ui]       + bf);
            float ig = sigmoidf_(sG[b * 32 + 8 + ui]   + bi);
            float cg = tanhf    (sG[b * 32 + 16 + ui]  + bc);
            float og = sigmoidf_(sG[b * 32 + 24 + ui]  + bo);
            c = fg * c + ig * cg;
            float h = og * tanhf(c);
            out[((size_t)b * SEQ + t) * HSZ + u] = h;
            __nv_bfloat16 hh = __float2bfloat16(h);
            g_hhi[wb][b * HSZ + u] = hh;
            g_hlo[wb][b * HSZ + u] = __float2bfloat16(h - __bfloat162float(hh));
            if (t == SEQ - 1 && write_final) {
                out[(size_t)BATCH * SEQ * HSZ + b * HSZ + u]               = h;
                out[(size_t)BATCH * SEQ * HSZ + BATCH * HSZ + b * HSZ + u] = c;
            }
        }

        // ---- software grid barrier ----
        __syncthreads();
        if (tid == 0) {
            __threadfence();
            atomicAdd(&g_bar, 1u);
            const unsigned tgt = (unsigned)NCTA * (unsigned)(t + 1);
            unsigned v;
            do {
                asm volatile("ld.acquire.gpu.u32 %0,[%1];" : "=r"(v) : "l"(&g_bar) : "memory");
            } while (v < tgt);
            __threadfence();
        }
        __syncthreads();
    }
}

// ---------------- launch ----------------
extern "C" void kernel_launch(void* const* d_in, const int* in_sizes, int n_in,
                              void* d_out, int out_size) {
    const float* x = nullptr;
    const float* W = nullptr;
    const float* bias = nullptr;
    for (int i = 0; i < n_in; i++) {
        if (in_sizes[i] == BATCH * SEQ * ISZ)      x = (const float*)d_in[i];
        else if (in_sizes[i] == KZ * GSZ)          W = (const float*)d_in[i];
        else if (in_sizes[i] == GSZ)               bias = (const float*)d_in[i];
    }
    float* out = (float*)d_out;
    const long long full = (long long)BATCH * SEQ * HSZ + 2LL * BATCH * HSZ;
    const int write_final = (out_size >= full) ? 1 : 0;

    cudaFuncSetAttribute(lstm_persist, cudaFuncAttributeMaxDynamicSharedMemorySize, SMEM_TOTAL);

    {
        int n4 = BATCH * SEQ * ISZ / 4;
        prep_x<<<(n4 + 255) / 256, 256>>>(x);
    }
    {
        long long n = (long long)NCTA * WORDS_PER_CTA;
        prep_w<<<(unsigned)((n + 255) / 256), 256>>>(W);
    }
    prep_state<<<(2 * BATCH * HSZ + 255) / 256, 256>>>();

    lstm_persist<<<NCTA, 256, SMEM_TOTAL>>>(bias, out, write_final);
}

// round 5
// speedup vs baseline: 2.6826x; 1.2573x over previous
#include <cuda_runtime.h>
#include <cuda_bf16.h>
#include <cstdint>

// ---------------- problem dims ----------------
#define BATCH 64
#define SEQ   512
#define ISZ   512
#define HSZ   1024
#define GSZ   4096
#define NCTA  128            // persistent CTAs
#define UPC   8              // hidden units per CTA (32 gate cols)
#define NK16H 64             // k16 tiles in K=1024 (h part)
#define NKTH  16             // k64 tiles per step
#define WORDS_H (NK16H * 4 * 32 * 2)   // 16384 u32 per W term per CTA
#define NK16X 96             // stacked k16 tiles for x GEMM (3 segs x 32)
#define WORDS_X (NK16X * 4 * 32 * 2)   // 24576 u32 per CTA-col-block

// recurrent smem layout (bytes)
#define SM_WLO   65536
#define SM_A     131072
#define A_MAT    9216            // 64 rows x 144B
#define A_STAGE  18432           // hi + lo
#define SMEM_TOTAL (131072 + 3 * A_STAGE)   // 186368

// ---------------- persistent device scratch ----------------
__device__ __align__(256) unsigned      g_Whf_hi[(size_t)NCTA * WORDS_H];  // 8 MB
__device__ __align__(256) unsigned      g_Whf_lo[(size_t)NCTA * WORDS_H];  // 8 MB
__device__ __align__(256) unsigned      g_Wxf[(size_t)NCTA * WORDS_X];     // 12.6 MB (hi,hi,lo stacked)
__device__ __align__(256) __nv_bfloat16 g_xhi[(size_t)BATCH * SEQ * ISZ];  // 32 MB
__device__ __align__(256) __nv_bfloat16 g_xlo[(size_t)BATCH * SEQ * ISZ];  // 32 MB
__device__ __align__(256) float         g_xg[(size_t)SEQ * NCTA * BATCH * 32]; // 512 MB
__device__ __align__(256) __nv_bfloat16 g_hhi[2][BATCH * HSZ];
__device__ __align__(256) __nv_bfloat16 g_hlo[2][BATCH * HSZ];
__device__ unsigned g_bar;

// ---------------- helpers ----------------
__device__ __forceinline__ void cp_async16_s(uint32_t dst_smem, const void* src) {
    asm volatile("cp.async.cg.shared.global [%0], [%1], 16;\n"
                 :: "r"(dst_smem), "l"(src) : "memory");
}
__device__ __forceinline__ void cp_commit() {
    asm volatile("cp.async.commit_group;\n" ::: "memory");
}
__device__ __forceinline__ float sigmoidf_(float v) { return 1.0f / (1.0f + expf(-v)); }

#define LDSM4(R, ADDR) \
    asm volatile("ldmatrix.sync.aligned.m8n8.x4.shared.b16 {%0,%1,%2,%3},[%4];" \
                 : "=r"((R)[0]), "=r"((R)[1]), "=r"((R)[2]), "=r"((R)[3]) : "r"(ADDR))

#define MMA_BF16(ACC, A, B0, B1) \
    asm volatile("mma.sync.aligned.m16n8k16.row.col.f32.bf16.bf16.f32 " \
                 "{%0,%1,%2,%3},{%4,%5,%6,%7},{%8,%9},{%0,%1,%2,%3};" \
                 : "+f"((ACC)[0]), "+f"((ACC)[1]), "+f"((ACC)[2]), "+f"((ACC)[3]) \
                 : "r"((A)[0]), "r"((A)[1]), "r"((A)[2]), "r"((A)[3]), "r"(B0), "r"(B1))

#define LDSV2(R0, R1, ADDR) \
    asm volatile("ld.shared.v2.u32 {%0,%1},[%2];" : "=r"(R0), "=r"(R1) : "r"(ADDR))

// ---------------- prep kernels ----------------
__global__ void prep_x(const float* __restrict__ x) {
    size_t i = (size_t)blockIdx.x * blockDim.x + threadIdx.x;
    size_t n4 = (size_t)BATCH * SEQ * ISZ / 4;
    if (i >= n4) return;
    float4 v = reinterpret_cast<const float4*>(x)[i];
    float vv[4] = {v.x, v.y, v.z, v.w};
    __nv_bfloat16 hi[4], lo[4];
#pragma unroll
    for (int j = 0; j < 4; j++) {
        hi[j] = __float2bfloat16(vv[j]);
        lo[j] = __float2bfloat16(vv[j] - __bfloat162float(hi[j]));
    }
    __nv_bfloat162* dh = reinterpret_cast<__nv_bfloat162*>(g_xhi);
    __nv_bfloat162* dl = reinterpret_cast<__nv_bfloat162*>(g_xlo);
    dh[i * 2]     = __nv_bfloat162(hi[0], hi[1]);
    dh[i * 2 + 1] = __nv_bfloat162(hi[2], hi[3]);
    dl[i * 2]     = __nv_bfloat162(lo[0], lo[1]);
    dl[i * 2 + 1] = __nv_bfloat162(lo[2], lo[3]);
}

// Wh fragments (K=1024, rows ISZ..ISZ+1023 of W), hi and lo arrays.
// word w = (((cb*64 + k16)*4 + n8)*32 + lane)*2 + q
__global__ void prep_wh(const float* __restrict__ W) {
    size_t w = (size_t)blockIdx.x * blockDim.x + threadIdx.x;
    if (w >= (size_t)NCTA * WORDS_H) return;
    int q    = (int)(w & 1);
    int lane = (int)((w >> 1) & 31);
    int n8   = (int)((w >> 6) & 3);
    int k16  = (int)((w >> 8) & 63);
    int cb   = (int)(w >> 14);
    int k  = k16 * 16 + (lane & 3) * 2 + q * 8;
    int nl = n8 * 8 + (lane >> 2);
    int col = (nl >> 3) * HSZ + cb * UPC + (nl & 7);
    float w0 = W[(size_t)(ISZ + k) * GSZ + col];
    float w1 = W[(size_t)(ISZ + k + 1) * GSZ + col];
    __nv_bfloat16 h0 = __float2bfloat16(w0), h1 = __float2bfloat16(w1);
    __nv_bfloat16 l0 = __float2bfloat16(w0 - __bfloat162float(h0));
    __nv_bfloat16 l1 = __float2bfloat16(w1 - __bfloat162float(h1));
    __nv_bfloat162 ph(h0, h1), pl(l0, l1);
    g_Whf_hi[w] = *reinterpret_cast<unsigned*>(&ph);
    g_Whf_lo[w] = *reinterpret_cast<unsigned*>(&pl);
}

// Wx fragments, K-stacked 3 segs (hi, hi, lo), rows 0..511 of W.
// word w = (((cb*96 + k16)*4 + n8)*32 + lane)*2 + q ; seg = k16/32
__global__ void prep_wx(const float* __restrict__ W) {
    size_t w = (size_t)blockIdx.x * blockDim.x + threadIdx.x;
    if (w >= (size_t)NCTA * WORDS_X) return;
    int q    = (int)(w & 1);
    int lane = (int)((w >> 1) & 31);
    int n8   = (int)((w >> 6) & 3);
    int k16s = (int)((w >> 8) % NK16X);
    int cb   = (int)((w >> 8) / NK16X);
    int seg  = k16s >> 5;
    int k    = (k16s & 31) * 16 + (lane & 3) * 2 + q * 8;
    int nl = n8 * 8 + (lane >> 2);
    int col = (nl >> 3) * HSZ + cb * UPC + (nl & 7);
    float w0 = W[(size_t)k * GSZ + col];
    float w1 = W[(size_t)(k + 1) * GSZ + col];
    __nv_bfloat16 v0, v1;
    if (seg < 2) { v0 = __float2bfloat16(w0); v1 = __float2bfloat16(w1); }
    else {
        __nv_bfloat16 h0 = __float2bfloat16(w0), h1 = __float2bfloat16(w1);
        v0 = __float2bfloat16(w0 - __bfloat162float(h0));
        v1 = __float2bfloat16(w1 - __bfloat162float(h1));
    }
    __nv_bfloat162 p(v0, v1);
    g_Wxf[w] = *reinterpret_cast<unsigned*>(&p);
}

__global__ void prep_state() {
    int i = blockIdx.x * blockDim.x + threadIdx.x;
    if (i < 2 * BATCH * HSZ) {
        (&g_hhi[0][0])[i] = __float2bfloat16(0.0f);
        (&g_hlo[0][0])[i] = __float2bfloat16(0.0f);
    }
    if (i == 0) g_bar = 0u;
}

// ---------------- xg precompute GEMM ----------------
// xg[t][cb][b][gc] = sum_k x[b,t,k]*Wx[k, perm(cb,gc)] + bias, 3-term bf16.
// grid (256 m-tiles, 128 cb), 256 threads. M-tile=128 tokens, N=32 cols, Keff=1536.
#define XG_A_STAGE 10240     // 128 rows x 80B
#define XG_B_STAGE 2048
__global__ void __launch_bounds__(256) xw_gemm(const float* __restrict__ bias) {
    __shared__ __align__(16) char smem[3 * XG_A_STAGE + 3 * XG_B_STAGE]; // 36864
    const uint32_t sA_u = (uint32_t)__cvta_generic_to_shared(smem);
    const uint32_t sB_u = sA_u + 3 * XG_A_STAGE;

    const int tid  = threadIdx.x;
    const int warp = tid >> 5;
    const int lane = tid & 31;
    const int bx   = blockIdx.x;     // m tile
    const int cb   = blockIdx.y;
    const int mw   = warp >> 1;      // 4 M-warps (32 rows each)
    const int nw   = warp & 1;       // 2 N-warps (16 cols each)

    float acc[2][2][4];
#pragma unroll
    for (int a = 0; a < 2; a++)
#pragma unroll
        for (int b = 0; b < 2; b++)
#pragma unroll
            for (int c = 0; c < 4; c++) acc[a][b][c] = 0.0f;

    auto load_tile = [&](int kt, int stage) {
        const int k0 = kt * 32;
        const int seg = k0 >> 9;
        const int off = k0 & 511;
        const __nv_bfloat16* base = (seg == 1) ? g_xlo : g_xhi;
        // A: 128 rows x 32 k (64B) = 512 chunks
#pragma unroll
        for (int j = 0; j < 2; j++) {
            int ch = tid + j * 256;
            int rr = ch >> 2, cc = ch & 3;
            cp_async16_s(sA_u + stage * XG_A_STAGE + rr * 80 + cc * 16,
                         base + ((size_t)(bx * 128 + rr)) * ISZ + off + cc * 8);
        }
        // B: 512 words = 128 chunks
        if (tid < 128) {
            const unsigned* src = g_Wxf + ((size_t)cb * NK16X + kt * 2) * 256 + tid * 4;
            cp_async16_s(sB_u + stage * XG_B_STAGE + tid * 16, src);
        }
        cp_commit();
    };

    load_tile(0, 0);
    load_tile(1, 1);

    const uint32_t arow = (uint32_t)((mw * 32 + (lane & 15)) * 80 + (lane >> 4) * 16);

    for (int kt0 = 0; kt0 < 48; kt0 += 3) {
#pragma unroll
        for (int j = 0; j < 3; j++) {
            const int kt = kt0 + j;
            if (kt == 47) { asm volatile("cp.async.wait_group 0;\n" ::: "memory"); }
            else          { asm volatile("cp.async.wait_group 1;\n" ::: "memory"); }
            __syncthreads();
            if (kt + 2 < 48) load_tile(kt + 2, (kt + 2) % 3);

            const int stage = kt % 3;
            const uint32_t Ab = sA_u + stage * XG_A_STAGE + arow;
            const uint32_t Bb = sB_u + stage * XG_B_STAGE + lane * 8;
#pragma unroll
            for (int sub = 0; sub < 2; sub++) {
                uint32_t a0[4], a1[4];
                LDSM4(a0, Ab + sub * 32);
                LDSM4(a1, Ab + 16 * 80 + sub * 32);
#pragma unroll
                for (int ni = 0; ni < 2; ni++) {
                    const int n8 = nw * 2 + ni;
                    uint32_t b0, b1;
                    LDSV2(b0, b1, Bb + (sub * 4 + n8) * 256);
                    MMA_BF16(acc[0][ni], a0, b0, b1);
                    MMA_BF16(acc[1][ni], a1, b0, b1);
                }
            }
        }
    }

    // epilogue: direct stores into permuted xg (+bias)
    const int g = lane >> 2, t4 = lane & 3;
#pragma unroll
    for (int ni = 0; ni < 2; ni++) {
        const int gc0 = nw * 16 + ni * 8 + t4 * 2;
        const float bv0 = bias[(gc0 >> 3) * HSZ + cb * UPC + (gc0 & 7)];
        const float bv1 = bias[((gc0 + 1) >> 3) * HSZ + cb * UPC + ((gc0 + 1) & 7)];
#pragma unroll
        for (int mi = 0; mi < 2; mi++) {
#pragma unroll
            for (int rr = 0; rr < 2; rr++) {
                const int r = mw * 32 + mi * 16 + rr * 8 + g;
                const int m = bx * 128 + r;
                const int b = m >> 9, t = m & 511;
                float* dst = g_xg + (((size_t)t * NCTA + cb) * BATCH + b) * 32 + gc0;
                dst[0] = acc[mi][ni][rr * 2]     + bv0;
                dst[1] = acc[mi][ni][rr * 2 + 1] + bv1;
            }
        }
    }
}

// ---------------- persistent recurrent kernel ----------------
// 128 CTAs x 512 threads. Wh fragments resident in SMEM. K=1024, 16 k64 tiles.
__global__ void __launch_bounds__(512, 1) lstm_persist(
    float* __restrict__ out, int write_final)
{
    extern __shared__ char smem[];
    float* sG = reinterpret_cast<float*>(smem + SM_A);   // overlays A stage 0

    const int tid  = threadIdx.x;
    const int warp = tid >> 5;
    const int lane = tid & 31;
    const int cb   = blockIdx.x;
    const int mw   = warp >> 2;          // 4 M-warps (16 rows)
    const int n8   = warp & 3;           // 4 N-warps (8 cols)
    const int wm   = mw * 16;

    // resident Wh fragments (once)
    {
        const uint4* sh = reinterpret_cast<const uint4*>(g_Whf_hi + (size_t)cb * WORDS_H);
        const uint4* sl = reinterpret_cast<const uint4*>(g_Whf_lo + (size_t)cb * WORDS_H);
        uint4* dh = reinterpret_cast<uint4*>(smem);
        uint4* dl = reinterpret_cast<uint4*>(smem + SM_WLO);
        for (int i = tid; i < WORDS_H / 4; i += 512) { dh[i] = sh[i]; dl[i] = sl[i]; }
    }

    const int ui = tid & 7;               // unit within CTA
    const int bb = tid >> 3;              // batch 0..63
    const int u  = cb * UPC + ui;
    float cst = 0.0f;

    const uint32_t sW_u = (uint32_t)__cvta_generic_to_shared(smem);
    const uint32_t sA_u = sW_u + SM_A;
    const uint32_t arow = (uint32_t)((wm + (lane & 15)) * 144 + (lane >> 4) * 16);
    // loader indices: 1024 chunks/stage (2 mats x 64 rows x 8 cc);
    // each of 512 threads issues 2 cp.asyncs (hi mat + lo mat).
    const int l_row = tid >> 3;      // 0..63
    const int l_cc  = tid & 7;       // 0..7

    __syncthreads();

    for (int t = 0; t < SEQ; t++) {
        const int rb = t & 1, wb = rb ^ 1;
        float acc[4] = {0.f, 0.f, 0.f, 0.f};

        auto load_tile = [&](int kt, int stage) {
            const int k0 = kt * 64;
            const size_t off = (size_t)l_row * HSZ + k0 + l_cc * 8;
            const uint32_t dst = sA_u + stage * A_STAGE + l_row * 144 + l_cc * 16;
            cp_async16_s(dst,         g_hhi[rb] + off);
            cp_async16_s(dst + A_MAT, g_hlo[rb] + off);
            cp_commit();
        };

        load_tile(0, 0);
        load_tile(1, 1);

#pragma unroll
        for (int kt = 0; kt < NKTH; kt++) {
            if (kt == NKTH - 1) { asm volatile("cp.async.wait_group 0;\n" ::: "memory"); }
            else                { asm volatile("cp.async.wait_group 1;\n" ::: "memory"); }
            __syncthreads();
            if (kt + 2 < NKTH) load_tile(kt + 2, (kt + 2) % 3);

            const uint32_t Ab = sA_u + (kt % 3) * A_STAGE + arow;
            const uint32_t Bb = sW_u + (kt * 4 * 4 + n8) * 256 + lane * 8;
#pragma unroll
            for (int sub = 0; sub < 4; sub++) {
                uint32_t ah[4], al[4];
                LDSM4(ah, Ab + sub * 32);
                LDSM4(al, Ab + A_MAT + sub * 32);
                uint32_t bh0, bh1, bl0, bl1;
                LDSV2(bh0, bh1, Bb + sub * 1024);
                LDSV2(bl0, bl1, Bb + sub * 1024 + SM_WLO);
                MMA_BF16(acc, ah, bh0, bh1);
                MMA_BF16(acc, al, bh0, bh1);
                MMA_BF16(acc, ah, bl0, bl1);
            }
        }

        // gate exchange via smem (overlays stage 0; MMA done)
        __syncthreads();
        {
            const int g = lane >> 2, t4 = lane & 3;
            const int c = n8 * 8 + t4 * 2;
            sG[(wm + g) * 32 + c]           = acc[0];
            sG[(wm + g) * 32 + c + 1]       = acc[1];
            sG[(wm + 8 + g) * 32 + c]       = acc[2];
            sG[(wm + 8 + g) * 32 + c + 1]   = acc[3];
        }
        __syncthreads();

        // cell update: thread owns (bb, ui)
        {
            const float* xg = g_xg + (((size_t)t * NCTA + cb) * BATCH + bb) * 32;
            float fg = sigmoidf_(sG[bb * 32 + ui]      + xg[ui]);
            float ig = sigmoidf_(sG[bb * 32 + 8 + ui]  + xg[8 + ui]);
            float cg = tanhf    (sG[bb * 32 + 16 + ui] + xg[16 + ui]);
            float og = sigmoidf_(sG[bb * 32 + 24 + ui] + xg[24 + ui]);
            cst = fg * cst + ig * cg;
            float h = og * tanhf(cst);
            out[((size_t)bb * SEQ + t) * HSZ + u] = h;
            __nv_bfloat16 hh = __float2bfloat16(h);
            g_hhi[wb][bb * HSZ + u] = hh;
            g_hlo[wb][bb * HSZ + u] = __float2bfloat16(h - __bfloat162float(hh));
            if (t == SEQ - 1 && write_final) {
                out[(size_t)BATCH * SEQ * HSZ + bb * HSZ + u]               = h;
                out[(size_t)BATCH * SEQ * HSZ + BATCH * HSZ + bb * HSZ + u] = cst;
            }
        }

        // grid barrier
        __syncthreads();
        if (tid == 0) {
            __threadfence();
            atomicAdd(&g_bar, 1u);
            const unsigned tgt = (unsigned)NCTA * (unsigned)(t + 1);
            unsigned v;
            do {
                asm volatile("ld.acquire.gpu.u32 %0,[%1];" : "=r"(v) : "l"(&g_bar) : "memory");
            } while (v < tgt);
            __threadfence();
        }
        __syncthreads();
    }
}

// ---------------- launch ----------------
extern "C" void kernel_launch(void* const* d_in, const int* in_sizes, int n_in,
                              void* d_out, int out_size) {
    const float* x = nullptr;
    const float* W = nullptr;
    const float* bias = nullptr;
    for (int i = 0; i < n_in; i++) {
        if (in_sizes[i] == BATCH * SEQ * ISZ)           x = (const float*)d_in[i];
        else if (in_sizes[i] == (ISZ + HSZ) * GSZ)      W = (const float*)d_in[i];
        else if (in_sizes[i] == GSZ)                    bias = (const float*)d_in[i];
    }
    float* out = (float*)d_out;
    const long long full = (long long)BATCH * SEQ * HSZ + 2LL * BATCH * HSZ;
    const int write_final = (out_size >= full) ? 1 : 0;

    cudaFuncSetAttribute(lstm_persist, cudaFuncAttributeMaxDynamicSharedMemorySize, SMEM_TOTAL);

    {
        int n4 = BATCH * SEQ * ISZ / 4;
        prep_x<<<(n4 + 255) / 256, 256>>>(x);
    }
    {
        long long n = (long long)NCTA * WORDS_H;
        prep_wh<<<(unsigned)((n + 255) / 256), 256>>>(W);
    }
    {
        long long n = (long long)NCTA * WORDS_X;
        prep_wx<<<(unsigned)((n + 255) / 256), 256>>>(W);
    }
    prep_state<<<(2 * BATCH * HSZ + 255) / 256, 256>>>();

    {
        dim3 grid(SEQ * BATCH / 128, NCTA);
        xw_gemm<<<grid, 256>>>(bias);
    }

    lstm_persist<<<NCTA, 512, SMEM_TOTAL>>>(out, write_final);
}

// round 6
// speedup vs baseline: 3.0217x; 1.1264x over previous
#include <cuda_runtime.h>
#include <cuda_bf16.h>
#include <cstdint>

// ---------------- problem dims ----------------
#define BATCH 64
#define SEQ   512
#define ISZ   512
#define HSZ   1024
#define GSZ   4096
#define NCTA  128            // persistent CTAs
#define UPC   8              // hidden units per CTA (32 gate cols)
#define NK16H 64             // k16 tiles in K=1024 (h part)
#define NKTH  8              // k128 tiles per step
#define WORDS_H (NK16H * 4 * 32 * 2)   // 16384 u32 per W term per CTA
#define NK16X 96             // stacked k16 tiles for x GEMM (3 segs x 32)
#define WORDS_X (NK16X * 4 * 32 * 2)   // 24576 u32 per CTA-col-block
#define CBQ   4              // cb blocks per xw CTA

// recurrent smem layout (bytes)
#define SM_WLO   65536
#define SM_A     131072
#define A_MAT    17408           // 64 rows x 272B (k128, +16B pad)
#define A_STAGE  34816           // hi + lo
#define SMEM_TOTAL (131072 + 2 * A_STAGE)   // 200704

// xw smem (dynamic): 3 stages A + 3 stages B
#define XG_A_STAGE 10240     // 128 rows x 80B
#define XG_B_STAGE 8192      // 4 cb x 2048B
#define XG_SMEM (3 * (XG_A_STAGE + XG_B_STAGE))   // 55296

// ---------------- persistent device scratch ----------------
__device__ __align__(256) unsigned      g_Whf_hi[(size_t)NCTA * WORDS_H];  // 8 MB
__device__ __align__(256) unsigned      g_Whf_lo[(size_t)NCTA * WORDS_H];  // 8 MB
__device__ __align__(256) unsigned      g_Wxf[(size_t)NCTA * WORDS_X];     // 12.6 MB
__device__ __align__(256) __nv_bfloat16 g_xhi[(size_t)BATCH * SEQ * ISZ];  // 32 MB
__device__ __align__(256) __nv_bfloat16 g_xlo[(size_t)BATCH * SEQ * ISZ];  // 32 MB
__device__ __align__(256) float         g_xg[(size_t)SEQ * NCTA * BATCH * 32]; // 512 MB
__device__ __align__(256) __nv_bfloat16 g_hhi[2][BATCH * HSZ];
__device__ __align__(256) __nv_bfloat16 g_hlo[2][BATCH * HSZ];
__device__ __align__(128) unsigned      g_flags[NCTA * 32];  // 1 padded slot per CTA

// ---------------- helpers ----------------
__device__ __forceinline__ void cp_async16_s(uint32_t dst_smem, const void* src) {
    asm volatile("cp.async.cg.shared.global [%0], [%1], 16;\n"
                 :: "r"(dst_smem), "l"(src) : "memory");
}
__device__ __forceinline__ void cp_commit() {
    asm volatile("cp.async.commit_group;\n" ::: "memory");
}
__device__ __forceinline__ float sigmoidf_(float v) { return 1.0f / (1.0f + expf(-v)); }

#define LDSM4(R, ADDR) \
    asm volatile("ldmatrix.sync.aligned.m8n8.x4.shared.b16 {%0,%1,%2,%3},[%4];" \
                 : "=r"((R)[0]), "=r"((R)[1]), "=r"((R)[2]), "=r"((R)[3]) : "r"(ADDR))

#define MMA_BF16(ACC, A, B0, B1) \
    asm volatile("mma.sync.aligned.m16n8k16.row.col.f32.bf16.bf16.f32 " \
                 "{%0,%1,%2,%3},{%4,%5,%6,%7},{%8,%9},{%0,%1,%2,%3};" \
                 : "+f"((ACC)[0]), "+f"((ACC)[1]), "+f"((ACC)[2]), "+f"((ACC)[3]) \
                 : "r"((A)[0]), "r"((A)[1]), "r"((A)[2]), "r"((A)[3]), "r"(B0), "r"(B1))

#define LDSV2(R0, R1, ADDR) \
    asm volatile("ld.shared.v2.u32 {%0,%1},[%2];" : "=r"(R0), "=r"(R1) : "r"(ADDR))

// ---------------- prep kernels ----------------
__global__ void prep_x(const float* __restrict__ x) {
    size_t i = (size_t)blockIdx.x * blockDim.x + threadIdx.x;
    size_t n4 = (size_t)BATCH * SEQ * ISZ / 4;
    if (i >= n4) return;
    float4 v = reinterpret_cast<const float4*>(x)[i];
    float vv[4] = {v.x, v.y, v.z, v.w};
    __nv_bfloat16 hi[4], lo[4];
#pragma unroll
    for (int j = 0; j < 4; j++) {
        hi[j] = __float2bfloat16(vv[j]);
        lo[j] = __float2bfloat16(vv[j] - __bfloat162float(hi[j]));
    }
    __nv_bfloat162* dh = reinterpret_cast<__nv_bfloat162*>(g_xhi);
    __nv_bfloat162* dl = reinterpret_cast<__nv_bfloat162*>(g_xlo);
    dh[i * 2]     = __nv_bfloat162(hi[0], hi[1]);
    dh[i * 2 + 1] = __nv_bfloat162(hi[2], hi[3]);
    dl[i * 2]     = __nv_bfloat162(lo[0], lo[1]);
    dl[i * 2 + 1] = __nv_bfloat162(lo[2], lo[3]);
}

// Wh fragments (K=1024, rows ISZ.. of W), hi and lo arrays.
// word w = (((cb*64 + k16)*4 + n8)*32 + lane)*2 + q
__global__ void prep_wh(const float* __restrict__ W) {
    size_t w = (size_t)blockIdx.x * blockDim.x + threadIdx.x;
    if (w >= (size_t)NCTA * WORDS_H) return;
    int q    = (int)(w & 1);
    int lane = (int)((w >> 1) & 31);
    int n8   = (int)((w >> 6) & 3);
    int k16  = (int)((w >> 8) & 63);
    int cb   = (int)(w >> 14);
    int k  = k16 * 16 + (lane & 3) * 2 + q * 8;
    int nl = n8 * 8 + (lane >> 2);
    int col = (nl >> 3) * HSZ + cb * UPC + (nl & 7);
    float w0 = W[(size_t)(ISZ + k) * GSZ + col];
    float w1 = W[(size_t)(ISZ + k + 1) * GSZ + col];
    __nv_bfloat16 h0 = __float2bfloat16(w0), h1 = __float2bfloat16(w1);
    __nv_bfloat16 l0 = __float2bfloat16(w0 - __bfloat162float(h0));
    __nv_bfloat16 l1 = __float2bfloat16(w1 - __bfloat162float(h1));
    __nv_bfloat162 ph(h0, h1), pl(l0, l1);
    g_Whf_hi[w] = *reinterpret_cast<unsigned*>(&ph);
    g_Whf_lo[w] = *reinterpret_cast<unsigned*>(&pl);
}

// Wx fragments, K-stacked 3 segs (hi, hi, lo), rows 0..511 of W.
__global__ void prep_wx(const float* __restrict__ W) {
    size_t w = (size_t)blockIdx.x * blockDim.x + threadIdx.x;
    if (w >= (size_t)NCTA * WORDS_X) return;
    int q    = (int)(w & 1);
    int lane = (int)((w >> 1) & 31);
    int n8   = (int)((w >> 6) & 3);
    int k16s = (int)((w >> 8) % NK16X);
    int cb   = (int)((w >> 8) / NK16X);
    int seg  = k16s >> 5;
    int k    = (k16s & 31) * 16 + (lane & 3) * 2 + q * 8;
    int nl = n8 * 8 + (lane >> 2);
    int col = (nl >> 3) * HSZ + cb * UPC + (nl & 7);
    float w0 = W[(size_t)k * GSZ + col];
    float w1 = W[(size_t)(k + 1) * GSZ + col];
    __nv_bfloat16 v0, v1;
    if (seg < 2) { v0 = __float2bfloat16(w0); v1 = __float2bfloat16(w1); }
    else {
        __nv_bfloat16 h0 = __float2bfloat16(w0), h1 = __float2bfloat16(w1);
        v0 = __float2bfloat16(w0 - __bfloat162float(h0));
        v1 = __float2bfloat16(w1 - __bfloat162float(h1));
    }
    __nv_bfloat162 p(v0, v1);
    g_Wxf[w] = *reinterpret_cast<unsigned*>(&p);
}

__global__ void prep_state() {
    int i = blockIdx.x * blockDim.x + threadIdx.x;
    if (i < 2 * BATCH * HSZ) {
        (&g_hhi[0][0])[i] = __float2bfloat16(0.0f);
        (&g_hlo[0][0])[i] = __float2bfloat16(0.0f);
    }
    if (i < NCTA * 32) g_flags[i] = 0u;
}

// ---------------- xg precompute GEMM ----------------
// grid (64 m-tiles... actually (SEQ*BATCH/128)=256 m-tiles, 32 cb-quads), 256 thr.
// Each CTA: M=128 tokens, N=128 (4 cb blocks), Keff=1536.
__global__ void __launch_bounds__(256) xw_gemm(const float* __restrict__ bias) {
    extern __shared__ char smem[];
    const uint32_t sA_u = (uint32_t)__cvta_generic_to_shared(smem);
    const uint32_t sB_u = sA_u + 3 * XG_A_STAGE;

    const int tid  = threadIdx.x;
    const int warp = tid >> 5;
    const int lane = tid & 31;
    const int bx   = blockIdx.x;            // m tile
    const int cb0  = blockIdx.y * CBQ;
    const int mw   = warp >> 1;              // 4 M-warps (32 rows each)
    const int nw   = warp & 1;               // 2 N-warps (64 cols each)

    float acc[2][8][4];
#pragma unroll
    for (int a = 0; a < 2; a++)
#pragma unroll
        for (int b = 0; b < 8; b++)
#pragma unroll
            for (int c = 0; c < 4; c++) acc[a][b][c] = 0.0f;

    auto load_tile = [&](int kt, int stage) {
        const int k0 = kt * 32;
        const int seg = k0 >> 9;
        const int off = k0 & 511;
        const __nv_bfloat16* base = (seg == 1) ? g_xlo : g_xhi;
        // A: 128 rows x 32 k = 512 chunks
#pragma unroll
        for (int j = 0; j < 2; j++) {
            int ch = tid + j * 256;
            int rr = ch >> 2, cc = ch & 3;
            cp_async16_s(sA_u + stage * XG_A_STAGE + rr * 80 + cc * 16,
                         base + ((size_t)(bx * 128 + rr)) * ISZ + off + cc * 8);
        }
        // B: 4 cb x 512 words = 512 chunks
#pragma unroll
        for (int j = 0; j < 2; j++) {
            int ch = tid + j * 256;
            int q = ch >> 7, ww = ch & 127;
            const unsigned* src = g_Wxf + ((size_t)(cb0 + q) * NK16X + kt * 2) * 256 + ww * 4;
            cp_async16_s(sB_u + stage * XG_B_STAGE + q * 2048 + ww * 16, src);
        }
        cp_commit();
    };

    load_tile(0, 0);
    load_tile(1, 1);

    const uint32_t arow = (uint32_t)((mw * 32 + (lane & 15)) * 80 + (lane >> 4) * 16);

    for (int kt0 = 0; kt0 < 48; kt0 += 3) {
#pragma unroll
        for (int j = 0; j < 3; j++) {
            const int kt = kt0 + j;
            if (kt == 47) { asm volatile("cp.async.wait_group 0;\n" ::: "memory"); }
            else          { asm volatile("cp.async.wait_group 1;\n" ::: "memory"); }
            __syncthreads();
            if (kt + 2 < 48) load_tile(kt + 2, (kt + 2) % 3);

            const int stage = kt % 3;
            const uint32_t Ab = sA_u + stage * XG_A_STAGE + arow;
            const uint32_t Bb = sB_u + stage * XG_B_STAGE + lane * 8;
#pragma unroll
            for (int sub = 0; sub < 2; sub++) {
                uint32_t a0[4], a1[4];
                LDSM4(a0, Ab + sub * 32);
                LDSM4(a1, Ab + 16 * 80 + sub * 32);
#pragma unroll
                for (int ni = 0; ni < 8; ni++) {
                    const int q = nw * 2 + (ni >> 2);
                    const int n8l = ni & 3;
                    uint32_t b0, b1;
                    LDSV2(b0, b1, Bb + q * 2048 + (sub * 4 + n8l) * 256);
                    MMA_BF16(acc[0][ni], a0, b0, b1);
                    MMA_BF16(acc[1][ni], a1, b0, b1);
                }
            }
        }
    }

    // epilogue: direct stores into permuted xg (+bias)
    const int g = lane >> 2, t4 = lane & 3;
#pragma unroll
    for (int ni = 0; ni < 8; ni++) {
        const int q   = nw * 2 + (ni >> 2);
        const int cb  = cb0 + q;
        const int gc0 = (ni & 3) * 8 + t4 * 2;
        const float bv0 = bias[(gc0 >> 3) * HSZ + cb * UPC + (gc0 & 7)];
        const float bv1 = bias[(gc0 >> 3) * HSZ + cb * UPC + (gc0 & 7) + 1];
#pragma unroll
        for (int mi = 0; mi < 2; mi++) {
#pragma unroll
            for (int rr = 0; rr < 2; rr++) {
                const int r = mw * 32 + mi * 16 + rr * 8 + g;
                const int m = bx * 128 + r;
                const int b = m >> 9, t = m & 511;
                float* dst = g_xg + (((size_t)t * NCTA + cb) * BATCH + b) * 32 + gc0;
                dst[0] = acc[mi][ni][rr * 2]     + bv0;
                dst[1] = acc[mi][ni][rr * 2 + 1] + bv1;
            }
        }
    }
}

// ---------------- persistent recurrent kernel ----------------
// 128 CTAs x 512 threads. Wh resident in SMEM. K=1024, 8 k128 tiles, 2 stages.
__global__ void __launch_bounds__(512, 1) lstm_persist(
    float* __restrict__ out, int write_final)
{
    extern __shared__ char smem[];
    float* sG = reinterpret_cast<float*>(smem + SM_A);   // overlays A stage 0

    const int tid  = threadIdx.x;
    const int warp = tid >> 5;
    const int lane = tid & 31;
    const int cb   = blockIdx.x;
    const int mw   = warp >> 2;          // 4 M-warps (16 rows)
    const int n8   = warp & 3;           // 4 N-warps (8 cols)
    const int wm   = mw * 16;

    // resident Wh fragments (once)
    {
        const uint4* sh = reinterpret_cast<const uint4*>(g_Whf_hi + (size_t)cb * WORDS_H);
        const uint4* sl = reinterpret_cast<const uint4*>(g_Whf_lo + (size_t)cb * WORDS_H);
        uint4* dh = reinterpret_cast<uint4*>(smem);
        uint4* dl = reinterpret_cast<uint4*>(smem + SM_WLO);
        for (int i = tid; i < WORDS_H / 4; i += 512) { dh[i] = sh[i]; dl[i] = sl[i]; }
    }

    const int ui = tid & 7;               // unit within CTA
    const int bb = tid >> 3;              // batch 0..63
    const int u  = cb * UPC + ui;
    float cst = 0.0f;

    const uint32_t sW_u = (uint32_t)__cvta_generic_to_shared(smem);
    const uint32_t sA_u = sW_u + SM_A;
    const uint32_t arow = (uint32_t)((wm + (lane & 15)) * 272 + (lane >> 4) * 16);
    const int l_row = tid >> 3;      // 0..63
    const int l_cc  = tid & 7;       // 0..7

    volatile unsigned* myflag = g_flags + cb * 32;

    __syncthreads();

    for (int t = 0; t < SEQ; t++) {
        const int rb = t & 1, wb = rb ^ 1;
        float acc[4] = {0.f, 0.f, 0.f, 0.f};

        auto load_tile = [&](int kt, int stage) {
            const int k0 = kt * 128;
            const size_t off = (size_t)l_row * HSZ + k0 + l_cc * 8;
            const uint32_t dst = sA_u + stage * A_STAGE + l_row * 272 + l_cc * 16;
            cp_async16_s(dst,               g_hhi[rb] + off);
            cp_async16_s(dst + 128,         g_hhi[rb] + off + 64);
            cp_async16_s(dst + A_MAT,       g_hlo[rb] + off);
            cp_async16_s(dst + A_MAT + 128, g_hlo[rb] + off + 64);
            cp_commit();
        };

        load_tile(0, 0);

        // xg prefetch (independent of h; hides DRAM latency until epilogue)
        const float* xgp = g_xg + (((size_t)t * NCTA + cb) * BATCH + bb) * 32;
        float xg0 = xgp[ui];
        float xg1 = xgp[8 + ui];
        float xg2 = xgp[16 + ui];
        float xg3 = xgp[24 + ui];

#pragma unroll
        for (int kt = 0; kt < NKTH; kt++) {
            asm volatile("cp.async.wait_group 0;\n" ::: "memory");
            __syncthreads();
            if (kt + 1 < NKTH) load_tile(kt + 1, (kt + 1) & 1);

            const uint32_t Ab = sA_u + (kt & 1) * A_STAGE + arow;
            const uint32_t Bb = sW_u + (kt * 32 + n8) * 256 + lane * 8;
#pragma unroll
            for (int sub = 0; sub < 8; sub++) {
                uint32_t ah[4], al[4];
                LDSM4(ah, Ab + sub * 32);
                LDSM4(al, Ab + A_MAT + sub * 32);
                uint32_t bh0, bh1, bl0, bl1;
                LDSV2(bh0, bh1, Bb + sub * 1024);
                LDSV2(bl0, bl1, Bb + sub * 1024 + SM_WLO);
                MMA_BF16(acc, ah, bh0, bh1);
                MMA_BF16(acc, al, bh0, bh1);
                MMA_BF16(acc, ah, bl0, bl1);
            }
        }

        // gate exchange via smem (stage 0 area free: last read was kt=6)
        {
            const int g = lane >> 2, t4 = lane & 3;
            const int c = n8 * 8 + t4 * 2;
            sG[(wm + g) * 32 + c]           = acc[0];
            sG[(wm + g) * 32 + c + 1]       = acc[1];
            sG[(wm + 8 + g) * 32 + c]       = acc[2];
            sG[(wm + 8 + g) * 32 + c + 1]   = acc[3];
        }
        __syncthreads();

        // cell update: thread owns (bb, ui)
        {
            float fg = sigmoidf_(sG[bb * 32 + ui]      + xg0);
            float ig = sigmoidf_(sG[bb * 32 + 8 + ui]  + xg1);
            float cg = tanhf    (sG[bb * 32 + 16 + ui] + xg2);
            float og = sigmoidf_(sG[bb * 32 + 24 + ui] + xg3);
            cst = fg * cst + ig * cg;
            float h = og * tanhf(cst);
            out[((size_t)bb * SEQ + t) * HSZ + u] = h;
            __nv_bfloat16 hh = __float2bfloat16(h);
            g_hhi[wb][bb * HSZ + u] = hh;
            g_hlo[wb][bb * HSZ + u] = __float2bfloat16(h - __bfloat162float(hh));
            if (t == SEQ - 1 && write_final) {
                out[(size_t)BATCH * SEQ * HSZ + bb * HSZ + u]               = h;
                out[(size_t)BATCH * SEQ * HSZ + BATCH * HSZ + bb * HSZ + u] = cst;
            }
        }

        // ---- flag-array grid barrier ----
        __syncthreads();
        if (tid == 0) {
            __threadfence();
            asm volatile("st.relaxed.gpu.u32 [%0], %1;"
                         :: "l"((unsigned*)myflag), "r"((unsigned)(t + 1)) : "memory");
        }
        if (tid < NCTA) {
            const unsigned* fl = (const unsigned*)(g_flags + tid * 32);
            unsigned v;
            do {
                asm volatile("ld.acquire.gpu.u32 %0, [%1];" : "=r"(v) : "l"(fl) : "memory");
            } while (v < (unsigned)(t + 1));
        }
        __syncthreads();
    }
}

// ---------------- launch ----------------
extern "C" void kernel_launch(void* const* d_in, const int* in_sizes, int n_in,
                              void* d_out, int out_size) {
    const float* x = nullptr;
    const float* W = nullptr;
    const float* bias = nullptr;
    for (int i = 0; i < n_in; i++) {
        if (in_sizes[i] == BATCH * SEQ * ISZ)           x = (const float*)d_in[i];
        else if (in_sizes[i] == (ISZ + HSZ) * GSZ)      W = (const float*)d_in[i];
        else if (in_sizes[i] == GSZ)                    bias = (const float*)d_in[i];
    }
    float* out = (float*)d_out;
    const long long full = (long long)BATCH * SEQ * HSZ + 2LL * BATCH * HSZ;
    const int write_final = (out_size >= full) ? 1 : 0;

    cudaFuncSetAttribute(lstm_persist, cudaFuncAttributeMaxDynamicSharedMemorySize, SMEM_TOTAL);
    cudaFuncSetAttribute(xw_gemm, cudaFuncAttributeMaxDynamicSharedMemorySize, XG_SMEM);

    {
        int n4 = BATCH * SEQ * ISZ / 4;
        prep_x<<<(n4 + 255) / 256, 256>>>(x);
    }
    {
        long long n = (long long)NCTA * WORDS_H;
        prep_wh<<<(unsigned)((n + 255) / 256), 256>>>(W);
    }
    {
        long long n = (long long)NCTA * WORDS_X;
        prep_wx<<<(unsigned)((n + 255) / 256), 256>>>(W);
    }
    prep_state<<<(2 * BATCH * HSZ + 255) / 256, 256>>>();

    {
        dim3 grid(SEQ * BATCH / 128, NCTA / CBQ);
        xw_gemm<<<grid, 256, XG_SMEM>>>(bias);
    }

    lstm_persist<<<NCTA, 512, SMEM_TOTAL>>>(out, write_final);
}

// round 7
// speedup vs baseline: 3.5680x; 1.1808x over previous
#include <cuda_runtime.h>
#include <cuda_bf16.h>
#include <cuda_fp16.h>
#include <cstdint>

// ---------------- problem dims ----------------
#define BATCH 64
#define SEQ   512
#define ISZ   512
#define HSZ   1024
#define GSZ   4096
#define NCTA  128            // persistent CTAs
#define UPC   8              // hidden units per CTA (32 gate cols)
#define WORDS_H (64 * 4 * 32 * 2)      // 16384 u32 (half2 frags) per W term per CTA
#define NK16X 96             // stacked k16 tiles for x GEMM (3 segs x 32)
#define WORDS_X (NK16X * 4 * 32 * 2)   // 24576 u32 per CTA-col-block
#define CBQ   4              // cb blocks per xw CTA

// recurrent smem layout (bytes)
#define SM_WLO   65536                  // W_lo frags at +64KB
#define SM_A     131072                 // A stages after 128KB of W
#define A_STRIDE 528                    // 512B data + 16B pad
#define A_STG    (64 * A_STRIDE)        // 33792 per stage
#define SMEM_TOTAL (SM_A + 2 * A_STG)   // 198656

// xw smem (dynamic): 3 stages A + 3 stages B  (unchanged, known good)
#define XG_A_STAGE 10240
#define XG_B_STAGE 8192
#define XG_SMEM (3 * (XG_A_STAGE + XG_B_STAGE))   // 55296

// ---------------- persistent device scratch ----------------
__device__ __align__(256) unsigned      g_Whf_hi[(size_t)NCTA * WORDS_H];  // 8 MB (fp16 pairs)
__device__ __align__(256) unsigned      g_Whf_lo[(size_t)NCTA * WORDS_H];  // 8 MB
__device__ __align__(256) unsigned      g_Wxf[(size_t)NCTA * WORDS_X];     // 12.6 MB (bf16, 3-seg)
__device__ __align__(256) __nv_bfloat16 g_xhi[(size_t)BATCH * SEQ * ISZ];  // 32 MB
__device__ __align__(256) __nv_bfloat16 g_xlo[(size_t)BATCH * SEQ * ISZ];  // 32 MB
__device__ __align__(256) float         g_xg[(size_t)SEQ * NCTA * BATCH * 32]; // 512 MB
__device__ __align__(256) __half        g_h[2][BATCH * HSZ];               // fp16 h, ping-pong
__device__ __align__(128) unsigned      g_flags[NCTA * 32];

// ---------------- helpers ----------------
__device__ __forceinline__ void cp_async16_s(uint32_t dst_smem, const void* src) {
    asm volatile("cp.async.cg.shared.global [%0], [%1], 16;\n"
                 :: "r"(dst_smem), "l"(src) : "memory");
}
__device__ __forceinline__ void cp_commit() {
    asm volatile("cp.async.commit_group;\n" ::: "memory");
}
__device__ __forceinline__ float sigmoidf_(float v) { return 1.0f / (1.0f + expf(-v)); }

#define LDSM4(R, ADDR) \
    asm volatile("ldmatrix.sync.aligned.m8n8.x4.shared.b16 {%0,%1,%2,%3},[%4];" \
                 : "=r"((R)[0]), "=r"((R)[1]), "=r"((R)[2]), "=r"((R)[3]) : "r"(ADDR))

#define MMA_BF16(ACC, A, B0, B1) \
    asm volatile("mma.sync.aligned.m16n8k16.row.col.f32.bf16.bf16.f32 " \
                 "{%0,%1,%2,%3},{%4,%5,%6,%7},{%8,%9},{%0,%1,%2,%3};" \
                 : "+f"((ACC)[0]), "+f"((ACC)[1]), "+f"((ACC)[2]), "+f"((ACC)[3]) \
                 : "r"((A)[0]), "r"((A)[1]), "r"((A)[2]), "r"((A)[3]), "r"(B0), "r"(B1))

#define MMA_F16(ACC, A, B0, B1) \
    asm volatile("mma.sync.aligned.m16n8k16.row.col.f32.f16.f16.f32 " \
                 "{%0,%1,%2,%3},{%4,%5,%6,%7},{%8,%9},{%0,%1,%2,%3};" \
                 : "+f"((ACC)[0]), "+f"((ACC)[1]), "+f"((ACC)[2]), "+f"((ACC)[3]) \
                 : "r"((A)[0]), "r"((A)[1]), "r"((A)[2]), "r"((A)[3]), "r"(B0), "r"(B1))

#define LDSV2(R0, R1, ADDR) \
    asm volatile("ld.shared.v2.u32 {%0,%1},[%2];" : "=r"(R0), "=r"(R1) : "r"(ADDR))

// ---------------- prep kernels ----------------
__global__ void prep_x(const float* __restrict__ x) {
    size_t i = (size_t)blockIdx.x * blockDim.x + threadIdx.x;
    size_t n4 = (size_t)BATCH * SEQ * ISZ / 4;
    if (i >= n4) return;
    float4 v = reinterpret_cast<const float4*>(x)[i];
    float vv[4] = {v.x, v.y, v.z, v.w};
    __nv_bfloat16 hi[4], lo[4];
#pragma unroll
    for (int j = 0; j < 4; j++) {
        hi[j] = __float2bfloat16(vv[j]);
        lo[j] = __float2bfloat16(vv[j] - __bfloat162float(hi[j]));
    }
    __nv_bfloat162* dh = reinterpret_cast<__nv_bfloat162*>(g_xhi);
    __nv_bfloat162* dl = reinterpret_cast<__nv_bfloat162*>(g_xlo);
    dh[i * 2]     = __nv_bfloat162(hi[0], hi[1]);
    dh[i * 2 + 1] = __nv_bfloat162(hi[2], hi[3]);
    dl[i * 2]     = __nv_bfloat162(lo[0], lo[1]);
    dl[i * 2 + 1] = __nv_bfloat162(lo[2], lo[3]);
}

// Wh fragments in fp16 hi/lo (K=1024, rows ISZ.. of W).
// word w = (((cb*64 + k16)*4 + n8)*32 + lane)*2 + q holds {B[k][n], B[k+1][n]} half2.
__global__ void prep_wh(const float* __restrict__ W) {
    size_t w = (size_t)blockIdx.x * blockDim.x + threadIdx.x;
    if (w >= (size_t)NCTA * WORDS_H) return;
    int q    = (int)(w & 1);
    int lane = (int)((w >> 1) & 31);
    int n8   = (int)((w >> 6) & 3);
    int k16  = (int)((w >> 8) & 63);
    int cb   = (int)(w >> 14);
    int k  = k16 * 16 + (lane & 3) * 2 + q * 8;
    int nl = n8 * 8 + (lane >> 2);
    int col = (nl >> 3) * HSZ + cb * UPC + (nl & 7);
    float w0 = W[(size_t)(ISZ + k) * GSZ + col];
    float w1 = W[(size_t)(ISZ + k + 1) * GSZ + col];
    __half h0 = __float2half_rn(w0), h1 = __float2half_rn(w1);
    __half l0 = __float2half_rn(w0 - __half2float(h0));
    __half l1 = __float2half_rn(w1 - __half2float(h1));
    __half2 ph = __halves2half2(h0, h1), pl = __halves2half2(l0, l1);
    g_Whf_hi[w] = *reinterpret_cast<unsigned*>(&ph);
    g_Whf_lo[w] = *reinterpret_cast<unsigned*>(&pl);
}

// Wx fragments (bf16, 3 K-stacked segs) — unchanged.
__global__ void prep_wx(const float* __restrict__ W) {
    size_t w = (size_t)blockIdx.x * blockDim.x + threadIdx.x;
    if (w >= (size_t)NCTA * WORDS_X) return;
    int q    = (int)(w & 1);
    int lane = (int)((w >> 1) & 31);
    int n8   = (int)((w >> 6) & 3);
    int k16s = (int)((w >> 8) % NK16X);
    int cb   = (int)((w >> 8) / NK16X);
    int seg  = k16s >> 5;
    int k    = (k16s & 31) * 16 + (lane & 3) * 2 + q * 8;
    int nl = n8 * 8 + (lane >> 2);
    int col = (nl >> 3) * HSZ + cb * UPC + (nl & 7);
    float w0 = W[(size_t)k * GSZ + col];
    float w1 = W[(size_t)(k + 1) * GSZ + col];
    __nv_bfloat16 v0, v1;
    if (seg < 2) { v0 = __float2bfloat16(w0); v1 = __float2bfloat16(w1); }
    else {
        __nv_bfloat16 h0 = __float2bfloat16(w0), h1 = __float2bfloat16(w1);
        v0 = __float2bfloat16(w0 - __bfloat162float(h0));
        v1 = __float2bfloat16(w1 - __bfloat162float(h1));
    }
    __nv_bfloat162 p(v0, v1);
    g_Wxf[w] = *reinterpret_cast<unsigned*>(&p);
}

__global__ void prep_state() {
    int i = blockIdx.x * blockDim.x + threadIdx.x;
    if (i < 2 * BATCH * HSZ) (&g_h[0][0])[i] = __float2half(0.0f);
    if (i < NCTA * 32) g_flags[i] = 0u;
}

// ---------------- xg precompute GEMM (bf16 3-term, unchanged) ----------------
__global__ void __launch_bounds__(256) xw_gemm(const float* __restrict__ bias) {
    extern __shared__ char smem[];
    const uint32_t sA_u = (uint32_t)__cvta_generic_to_shared(smem);
    const uint32_t sB_u = sA_u + 3 * XG_A_STAGE;

    const int tid  = threadIdx.x;
    const int warp = tid >> 5;
    const int lane = tid & 31;
    const int bx   = blockIdx.x;
    const int cb0  = blockIdx.y * CBQ;
    const int mw   = warp >> 1;
    const int nw   = warp & 1;

    float acc[2][8][4];
#pragma unroll
    for (int a = 0; a < 2; a++)
#pragma unroll
        for (int b = 0; b < 8; b++)
#pragma unroll
            for (int c = 0; c < 4; c++) acc[a][b][c] = 0.0f;

    auto load_tile = [&](int kt, int stage) {
        const int k0 = kt * 32;
        const int seg = k0 >> 9;
        const int off = k0 & 511;
        const __nv_bfloat16* base = (seg == 1) ? g_xlo : g_xhi;
#pragma unroll
        for (int j = 0; j < 2; j++) {
            int ch = tid + j * 256;
            int rr = ch >> 2, cc = ch & 3;
            cp_async16_s(sA_u + stage * XG_A_STAGE + rr * 80 + cc * 16,
                         base + ((size_t)(bx * 128 + rr)) * ISZ + off + cc * 8);
        }
#pragma unroll
        for (int j = 0; j < 2; j++) {
            int ch = tid + j * 256;
            int q = ch >> 7, ww = ch & 127;
            const unsigned* src = g_Wxf + ((size_t)(cb0 + q) * NK16X + kt * 2) * 256 + ww * 4;
            cp_async16_s(sB_u + stage * XG_B_STAGE + q * 2048 + ww * 16, src);
        }
        cp_commit();
    };

    load_tile(0, 0);
    load_tile(1, 1);

    const uint32_t arow = (uint32_t)((mw * 32 + (lane & 15)) * 80 + (lane >> 4) * 16);

    for (int kt0 = 0; kt0 < 48; kt0 += 3) {
#pragma unroll
        for (int j = 0; j < 3; j++) {
            const int kt = kt0 + j;
            if (kt == 47) { asm volatile("cp.async.wait_group 0;\n" ::: "memory"); }
            else          { asm volatile("cp.async.wait_group 1;\n" ::: "memory"); }
            __syncthreads();
            if (kt + 2 < 48) load_tile(kt + 2, (kt + 2) % 3);

            const int stage = kt % 3;
            const uint32_t Ab = sA_u + stage * XG_A_STAGE + arow;
            const uint32_t Bb = sB_u + stage * XG_B_STAGE + lane * 8;
#pragma unroll
            for (int sub = 0; sub < 2; sub++) {
                uint32_t a0[4], a1[4];
                LDSM4(a0, Ab + sub * 32);
                LDSM4(a1, Ab + 16 * 80 + sub * 32);
#pragma unroll
                for (int ni = 0; ni < 8; ni++) {
                    const int q = nw * 2 + (ni >> 2);
                    const int n8l = ni & 3;
                    uint32_t b0, b1;
                    LDSV2(b0, b1, Bb + q * 2048 + (sub * 4 + n8l) * 256);
                    MMA_BF16(acc[0][ni], a0, b0, b1);
                    MMA_BF16(acc[1][ni], a1, b0, b1);
                }
            }
        }
    }

    const int g = lane >> 2, t4 = lane & 3;
#pragma unroll
    for (int ni = 0; ni < 8; ni++) {
        const int q   = nw * 2 + (ni >> 2);
        const int cb  = cb0 + q;
        const int gc0 = (ni & 3) * 8 + t4 * 2;
        const float bv0 = bias[(gc0 >> 3) * HSZ + cb * UPC + (gc0 & 7)];
        const float bv1 = bias[(gc0 >> 3) * HSZ + cb * UPC + (gc0 & 7) + 1];
#pragma unroll
        for (int mi = 0; mi < 2; mi++) {
#pragma unroll
            for (int rr = 0; rr < 2; rr++) {
                const int r = mw * 32 + mi * 16 + rr * 8 + g;
                const int m = bx * 128 + r;
                const int b = m >> 9, t = m & 511;
                float* dst = g_xg + (((size_t)t * NCTA + cb) * BATCH + b) * 32 + gc0;
                dst[0] = acc[mi][ni][rr * 2]     + bv0;
                dst[1] = acc[mi][ni][rr * 2 + 1] + bv1;
            }
        }
    }
}

// ---------------- persistent recurrent kernel (fp16 2-term, split-K) -------
// 128 CTAs x 512 threads (16 warps = 2M x 2N x 4K). W frags resident in SMEM.
// K=1024 streamed as 4 x k256 A-stages, 2-stage pipeline. Warp (kw,mw,nw)
// computes m32 x n16 over its k64 slice of each stage; 4 K-partials reduced
// through padded smem at step end.
__global__ void __launch_bounds__(512, 1) lstm_persist(
    float* __restrict__ out, int write_final)
{
    extern __shared__ char smem[];
    float* sG4 = reinterpret_cast<float*>(smem + SM_A);   // [4][64][33] overlay on A stage 0

    const int tid  = threadIdx.x;
    const int warp = tid >> 5;
    const int lane = tid & 31;
    const int cb   = blockIdx.x;
    const int kw   = warp & 3;           // K slice
    const int mw   = (warp >> 2) & 1;    // M half (m32)
    const int nw   = warp >> 3;          // N half (n16)

    // resident W fragment preload (once): hi 64KB + lo 64KB
    {
        const uint4* sh = reinterpret_cast<const uint4*>(g_Whf_hi + (size_t)cb * WORDS_H);
        const uint4* sl = reinterpret_cast<const uint4*>(g_Whf_lo + (size_t)cb * WORDS_H);
        uint4* dh = reinterpret_cast<uint4*>(smem);
        uint4* dl = reinterpret_cast<uint4*>(smem + SM_WLO);
        for (int i = tid; i < WORDS_H / 4; i += 512) { dh[i] = sh[i]; dl[i] = sl[i]; }
    }

    const int ui = tid & 7;
    const int bb = tid >> 3;             // 0..63 (also loader row)
    const int u  = cb * UPC + ui;
    float cst = 0.0f;

    const uint32_t sW_u = (uint32_t)__cvta_generic_to_shared(smem);
    const uint32_t sA_u = sW_u + SM_A;
    // ldmatrix base: row = (lane&15), col byte = kw*128 + (lane>>4)*16
    const uint32_t abase0 = (uint32_t)((lane & 15) * A_STRIDE + kw * 128 + (lane >> 4) * 16);
    const int l_cc = tid & 7;            // loader: 8 threads x 64B per row

    __syncthreads();

    for (int t = 0; t < SEQ; t++) {
        const int rb = t & 1, wb = rb ^ 1;
        float acc[2][2][4];
#pragma unroll
        for (int a = 0; a < 2; a++)
#pragma unroll
            for (int b = 0; b < 2; b++)
#pragma unroll
                for (int c = 0; c < 4; c++) acc[a][b][c] = 0.0f;

        auto load_stage = [&](int s, int stage) {
            const __half* src = g_h[rb] + (size_t)bb * HSZ + s * 256 + l_cc * 32;
            const uint32_t dst = sA_u + stage * A_STG + bb * A_STRIDE + l_cc * 64;
#pragma unroll
            for (int j = 0; j < 4; j++)
                cp_async16_s(dst + j * 16, src + j * 8);
            cp_commit();
        };

        load_stage(0, 0);

        // xg prefetch (hides DRAM latency until epilogue)
        const float* xgp = g_xg + (((size_t)t * NCTA + cb) * BATCH + bb) * 32;
        float xg0 = xgp[ui];
        float xg1 = xgp[8 + ui];
        float xg2 = xgp[16 + ui];
        float xg3 = xgp[24 + ui];

#pragma unroll
        for (int s = 0; s < 4; s++) {
            asm volatile("cp.async.wait_group 0;\n" ::: "memory");
            __syncthreads();
            if (s + 1 < 4) load_stage(s + 1, (s + 1) & 1);

            const uint32_t Ab = sA_u + (s & 1) * A_STG + abase0;
#pragma unroll
            for (int j = 0; j < 4; j++) {
                uint32_t a0[4], a1[4];
                LDSM4(a0, Ab + (mw * 2 + 0) * 16 * A_STRIDE + j * 32);
                LDSM4(a1, Ab + (mw * 2 + 1) * 16 * A_STRIDE + j * 32);
                const int k16g = s * 16 + kw * 4 + j;
#pragma unroll
                for (int ni = 0; ni < 2; ni++) {
                    const int n8g = nw * 2 + ni;
                    const uint32_t Bb = sW_u + (uint32_t)((k16g * 4 + n8g) * 256 + lane * 8);
                    uint32_t bh0, bh1, bl0, bl1;
                    LDSV2(bh0, bh1, Bb);
                    LDSV2(bl0, bl1, Bb + SM_WLO);
                    MMA_F16(acc[0][ni], a0, bh0, bh1);
                    MMA_F16(acc[1][ni], a1, bh0, bh1);
                    MMA_F16(acc[0][ni], a0, bl0, bl1);
                    MMA_F16(acc[1][ni], a1, bl0, bl1);
                }
            }
        }

        // K-partial store into padded smem [4][64][33] (overlay on A stage 0;
        // stage 0 last read at s=2, all warps past s=3's top sync).
        {
            const int g = lane >> 2, t4 = lane & 3;
#pragma unroll
            for (int mi = 0; mi < 2; mi++)
#pragma unroll
                for (int ni = 0; ni < 2; ni++) {
                    const int r = (mw * 2 + mi) * 16 + g;
                    const int c = (nw * 2 + ni) * 8 + t4 * 2;
                    float* p = sG4 + (kw * 64 + r) * 33 + c;
                    p[0]        = acc[mi][ni][0];
                    p[1]        = acc[mi][ni][1];
                    p[8 * 33]   = acc[mi][ni][2];
                    p[8 * 33 + 1] = acc[mi][ni][3];
                }
        }
        __syncthreads();

        // reduce 4 K-partials + cell update: thread owns (bb, ui)
        {
            float gf = 0.f, gi = 0.f, gc = 0.f, go = 0.f;
#pragma unroll
            for (int k = 0; k < 4; k++) {
                const float* p = sG4 + (k * 64 + bb) * 33;
                gf += p[ui];
                gi += p[8 + ui];
                gc += p[16 + ui];
                go += p[24 + ui];
            }
            float fg = sigmoidf_(gf + xg0);
            float ig = sigmoidf_(gi + xg1);
            float cg = tanhf    (gc + xg2);
            float og = sigmoidf_(go + xg3);
            cst = fg * cst + ig * cg;
            float h = og * tanhf(cst);
            out[((size_t)bb * SEQ + t) * HSZ + u] = h;
            g_h[wb][bb * HSZ + u] = __float2half_rn(h);
            if (t == SEQ - 1 && write_final) {
                out[(size_t)BATCH * SEQ * HSZ + bb * HSZ + u]               = h;
                out[(size_t)BATCH * SEQ * HSZ + BATCH * HSZ + bb * HSZ + u] = cst;
            }
        }

        // flag-array grid barrier
        __syncthreads();
        if (tid == 0) {
            __threadfence();
            asm volatile("st.relaxed.gpu.u32 [%0], %1;"
                         :: "l"(g_flags + cb * 32), "r"((unsigned)(t + 1)) : "memory");
        }
        if (tid < NCTA) {
            const unsigned* fl = (const unsigned*)(g_flags + tid * 32);
            unsigned v;
            do {
                asm volatile("ld.acquire.gpu.u32 %0, [%1];" : "=r"(v) : "l"(fl) : "memory");
            } while (v < (unsigned)(t + 1));
        }
        __syncthreads();
    }
}

// ---------------- launch ----------------
extern "C" void kernel_launch(void* const* d_in, const int* in_sizes, int n_in,
                              void* d_out, int out_size) {
    const float* x = nullptr;
    const float* W = nullptr;
    const float* bias = nullptr;
    for (int i = 0; i < n_in; i++) {
        if (in_sizes[i] == BATCH * SEQ * ISZ)           x = (const float*)d_in[i];
        else if (in_sizes[i] == (ISZ + HSZ) * GSZ)      W = (const float*)d_in[i];
        else if (in_sizes[i] == GSZ)                    bias = (const float*)d_in[i];
    }
    float* out = (float*)d_out;
    const long long full = (long long)BATCH * SEQ * HSZ + 2LL * BATCH * HSZ;
    const int write_final = (out_size >= full) ? 1 : 0;

    cudaFuncSetAttribute(lstm_persist, cudaFuncAttributeMaxDynamicSharedMemorySize, SMEM_TOTAL);
    cudaFuncSetAttribute(xw_gemm, cudaFuncAttributeMaxDynamicSharedMemorySize, XG_SMEM);

    {
        int n4 = BATCH * SEQ * ISZ / 4;
        prep_x<<<(n4 + 255) / 256, 256>>>(x);
    }
    {
        long long n = (long long)NCTA * WORDS_H;
        prep_wh<<<(unsigned)((n + 255) / 256), 256>>>(W);
    }
    {
        long long n = (long long)NCTA * WORDS_X;
        prep_wx<<<(unsigned)((n + 255) / 256), 256>>>(W);
    }
    prep_state<<<(2 * BATCH * HSZ + 255) / 256, 256>>>();

    {
        dim3 grid(SEQ * BATCH / 128, NCTA / CBQ);
        xw_gemm<<<grid, 256, XG_SMEM>>>(bias);
    }

    lstm_persist<<<NCTA, 512, SMEM_TOTAL>>>(out, write_final);
}

// round 8
// speedup vs baseline: 4.4237x; 1.2398x over previous
#include <cuda_runtime.h>
#include <cuda_bf16.h>
#include <cuda_fp16.h>
#include <cstdint>

// ---------------- problem dims ----------------
#define BATCH 64
#define SEQ   512
#define ISZ   512
#define HSZ   1024
#define GSZ   4096
#define NCTA  128            // persistent CTAs
#define UPC   8              // hidden units per CTA (32 gate cols)
#define WORDS_H (64 * 4 * 32 * 2)      // 16384 u32 (half2 frags) per CTA (1 term)
#define NK16X 96             // stacked k16 tiles for x GEMM (3 segs x 32)
#define WORDS_X (NK16X * 4 * 32 * 2)   // 24576 u32 per CTA-col-block
#define CBQ   4              // cb blocks per xw CTA

// recurrent smem layout (bytes): W 64KB, then 2 A stages of k512
#define SM_A     65536
#define A_STRIDE 1040                   // 1024B data + 16B pad
#define A_STG    (64 * A_STRIDE)        // 66560 per stage
#define SMEM_TOTAL (SM_A + 2 * A_STG)   // 198656

// xw smem (dynamic): 3 stages A + 3 stages B  (unchanged, known good)
#define XG_A_STAGE 10240
#define XG_B_STAGE 8192
#define XG_SMEM (3 * (XG_A_STAGE + XG_B_STAGE))   // 55296

// ---------------- persistent device scratch ----------------
__device__ __align__(256) unsigned      g_Whf[(size_t)NCTA * WORDS_H];     // 8 MB (fp16 pairs)
__device__ __align__(256) unsigned      g_Wxf[(size_t)NCTA * WORDS_X];     // 12.6 MB (bf16, 3-seg)
__device__ __align__(256) __nv_bfloat16 g_xhi[(size_t)BATCH * SEQ * ISZ];  // 32 MB
__device__ __align__(256) __nv_bfloat16 g_xlo[(size_t)BATCH * SEQ * ISZ];  // 32 MB
__device__ __align__(256) float         g_xg[(size_t)SEQ * NCTA * BATCH * 32]; // 512 MB
__device__ __align__(256) __half        g_h[2][BATCH * HSZ];               // fp16 h, ping-pong
__device__ __align__(128) unsigned      g_flags[NCTA * 32];

// ---------------- helpers ----------------
__device__ __forceinline__ void cp_async16_s(uint32_t dst_smem, const void* src) {
    asm volatile("cp.async.cg.shared.global [%0], [%1], 16;\n"
                 :: "r"(dst_smem), "l"(src) : "memory");
}
__device__ __forceinline__ void cp_commit() {
    asm volatile("cp.async.commit_group;\n" ::: "memory");
}
__device__ __forceinline__ float sigmoidf_(float v) { return 1.0f / (1.0f + expf(-v)); }

#define LDSM4(R, ADDR) \
    asm volatile("ldmatrix.sync.aligned.m8n8.x4.shared.b16 {%0,%1,%2,%3},[%4];" \
                 : "=r"((R)[0]), "=r"((R)[1]), "=r"((R)[2]), "=r"((R)[3]) : "r"(ADDR))

#define MMA_BF16(ACC, A, B0, B1) \
    asm volatile("mma.sync.aligned.m16n8k16.row.col.f32.bf16.bf16.f32 " \
                 "{%0,%1,%2,%3},{%4,%5,%6,%7},{%8,%9},{%0,%1,%2,%3};" \
                 : "+f"((ACC)[0]), "+f"((ACC)[1]), "+f"((ACC)[2]), "+f"((ACC)[3]) \
                 : "r"((A)[0]), "r"((A)[1]), "r"((A)[2]), "r"((A)[3]), "r"(B0), "r"(B1))

#define MMA_F16(ACC, A, B0, B1) \
    asm volatile("mma.sync.aligned.m16n8k16.row.col.f32.f16.f16.f32 " \
                 "{%0,%1,%2,%3},{%4,%5,%6,%7},{%8,%9},{%0,%1,%2,%3};" \
                 : "+f"((ACC)[0]), "+f"((ACC)[1]), "+f"((ACC)[2]), "+f"((ACC)[3]) \
                 : "r"((A)[0]), "r"((A)[1]), "r"((A)[2]), "r"((A)[3]), "r"(B0), "r"(B1))

#define LDSV2(R0, R1, ADDR) \
    asm volatile("ld.shared.v2.u32 {%0,%1},[%2];" : "=r"(R0), "=r"(R1) : "r"(ADDR))

// ---------------- prep kernels ----------------
__global__ void prep_x(const float* __restrict__ x) {
    size_t i = (size_t)blockIdx.x * blockDim.x + threadIdx.x;
    size_t n4 = (size_t)BATCH * SEQ * ISZ / 4;
    if (i >= n4) return;
    float4 v = reinterpret_cast<const float4*>(x)[i];
    float vv[4] = {v.x, v.y, v.z, v.w};
    __nv_bfloat16 hi[4], lo[4];
#pragma unroll
    for (int j = 0; j < 4; j++) {
        hi[j] = __float2bfloat16(vv[j]);
        lo[j] = __float2bfloat16(vv[j] - __bfloat162float(hi[j]));
    }
    __nv_bfloat162* dh = reinterpret_cast<__nv_bfloat162*>(g_xhi);
    __nv_bfloat162* dl = reinterpret_cast<__nv_bfloat162*>(g_xlo);
    dh[i * 2]     = __nv_bfloat162(hi[0], hi[1]);
    dh[i * 2 + 1] = __nv_bfloat162(hi[2], hi[3]);
    dl[i * 2]     = __nv_bfloat162(lo[0], lo[1]);
    dl[i * 2 + 1] = __nv_bfloat162(lo[2], lo[3]);
}

// Wh fragments in fp16, single term (K=1024, rows ISZ.. of W).
// word w = (((cb*64 + k16)*4 + n8)*32 + lane)*2 + q holds {B[k][n], B[k+1][n]} half2.
__global__ void prep_wh(const float* __restrict__ W) {
    size_t w = (size_t)blockIdx.x * blockDim.x + threadIdx.x;
    if (w >= (size_t)NCTA * WORDS_H) return;
    int q    = (int)(w & 1);
    int lane = (int)((w >> 1) & 31);
    int n8   = (int)((w >> 6) & 3);
    int k16  = (int)((w >> 8) & 63);
    int cb   = (int)(w >> 14);
    int k  = k16 * 16 + (lane & 3) * 2 + q * 8;
    int nl = n8 * 8 + (lane >> 2);
    int col = (nl >> 3) * HSZ + cb * UPC + (nl & 7);
    __half h0 = __float2half_rn(W[(size_t)(ISZ + k) * GSZ + col]);
    __half h1 = __float2half_rn(W[(size_t)(ISZ + k + 1) * GSZ + col]);
    __half2 ph = __halves2half2(h0, h1);
    g_Whf[w] = *reinterpret_cast<unsigned*>(&ph);
}

// Wx fragments (bf16, 3 K-stacked segs) — unchanged.
__global__ void prep_wx(const float* __restrict__ W) {
    size_t w = (size_t)blockIdx.x * blockDim.x + threadIdx.x;
    if (w >= (size_t)NCTA * WORDS_X) return;
    int q    = (int)(w & 1);
    int lane = (int)((w >> 1) & 31);
    int n8   = (int)((w >> 6) & 3);
    int k16s = (int)((w >> 8) % NK16X);
    int cb   = (int)((w >> 8) / NK16X);
    int seg  = k16s >> 5;
    int k    = (k16s & 31) * 16 + (lane & 3) * 2 + q * 8;
    int nl = n8 * 8 + (lane >> 2);
    int col = (nl >> 3) * HSZ + cb * UPC + (nl & 7);
    float w0 = W[(size_t)k * GSZ + col];
    float w1 = W[(size_t)(k + 1) * GSZ + col];
    __nv_bfloat16 v0, v1;
    if (seg < 2) { v0 = __float2bfloat16(w0); v1 = __float2bfloat16(w1); }
    else {
        __nv_bfloat16 h0 = __float2bfloat16(w0), h1 = __float2bfloat16(w1);
        v0 = __float2bfloat16(w0 - __bfloat162float(h0));
        v1 = __float2bfloat16(w1 - __bfloat162float(h1));
    }
    __nv_bfloat162 p(v0, v1);
    g_Wxf[w] = *reinterpret_cast<unsigned*>(&p);
}

__global__ void prep_state() {
    int i = blockIdx.x * blockDim.x + threadIdx.x;
    if (i < 2 * BATCH * HSZ) (&g_h[0][0])[i] = __float2half(0.0f);
    if (i < NCTA * 32) g_flags[i] = 0u;
}

// ---------------- xg precompute GEMM (bf16 3-term, unchanged) ----------------
__global__ void __launch_bounds__(256) xw_gemm(const float* __restrict__ bias) {
    extern __shared__ char smem[];
    const uint32_t sA_u = (uint32_t)__cvta_generic_to_shared(smem);
    const uint32_t sB_u = sA_u + 3 * XG_A_STAGE;

    const int tid  = threadIdx.x;
    const int warp = tid >> 5;
    const int lane = tid & 31;
    const int bx   = blockIdx.x;
    const int cb0  = blockIdx.y * CBQ;
    const int mw   = warp >> 1;
    const int nw   = warp & 1;

    float acc[2][8][4];
#pragma unroll
    for (int a = 0; a < 2; a++)
#pragma unroll
        for (int b = 0; b < 8; b++)
#pragma unroll
            for (int c = 0; c < 4; c++) acc[a][b][c] = 0.0f;

    auto load_tile = [&](int kt, int stage) {
        const int k0 = kt * 32;
        const int seg = k0 >> 9;
        const int off = k0 & 511;
        const __nv_bfloat16* base = (seg == 1) ? g_xlo : g_xhi;
#pragma unroll
        for (int j = 0; j < 2; j++) {
            int ch = tid + j * 256;
            int rr = ch >> 2, cc = ch & 3;
            cp_async16_s(sA_u + stage * XG_A_STAGE + rr * 80 + cc * 16,
                         base + ((size_t)(bx * 128 + rr)) * ISZ + off + cc * 8);
        }
#pragma unroll
        for (int j = 0; j < 2; j++) {
            int ch = tid + j * 256;
            int q = ch >> 7, ww = ch & 127;
            const unsigned* src = g_Wxf + ((size_t)(cb0 + q) * NK16X + kt * 2) * 256 + ww * 4;
            cp_async16_s(sB_u + stage * XG_B_STAGE + q * 2048 + ww * 16, src);
        }
        cp_commit();
    };

    load_tile(0, 0);
    load_tile(1, 1);

    const uint32_t arow = (uint32_t)((mw * 32 + (lane & 15)) * 80 + (lane >> 4) * 16);

    for (int kt0 = 0; kt0 < 48; kt0 += 3) {
#pragma unroll
        for (int j = 0; j < 3; j++) {
            const int kt = kt0 + j;
            if (kt == 47) { asm volatile("cp.async.wait_group 0;\n" ::: "memory"); }
            else          { asm volatile("cp.async.wait_group 1;\n" ::: "memory"); }
            __syncthreads();
            if (kt + 2 < 48) load_tile(kt + 2, (kt + 2) % 3);

            const int stage = kt % 3;
            const uint32_t Ab = sA_u + stage * XG_A_STAGE + arow;
            const uint32_t Bb = sB_u + stage * XG_B_STAGE + lane * 8;
#pragma unroll
            for (int sub = 0; sub < 2; sub++) {
                uint32_t a0[4], a1[4];
                LDSM4(a0, Ab + sub * 32);
                LDSM4(a1, Ab + 16 * 80 + sub * 32);
#pragma unroll
                for (int ni = 0; ni < 8; ni++) {
                    const int q = nw * 2 + (ni >> 2);
                    const int n8l = ni & 3;
                    uint32_t b0, b1;
                    LDSV2(b0, b1, Bb + q * 2048 + (sub * 4 + n8l) * 256);
                    MMA_BF16(acc[0][ni], a0, b0, b1);
                    MMA_BF16(acc[1][ni], a1, b0, b1);
                }
            }
        }
    }

    const int g = lane >> 2, t4 = lane & 3;
#pragma unroll
    for (int ni = 0; ni < 8; ni++) {
        const int q   = nw * 2 + (ni >> 2);
        const int cb  = cb0 + q;
        const int gc0 = (ni & 3) * 8 + t4 * 2;
        const float bv0 = bias[(gc0 >> 3) * HSZ + cb * UPC + (gc0 & 7)];
        const float bv1 = bias[(gc0 >> 3) * HSZ + cb * UPC + (gc0 & 7) + 1];
#pragma unroll
        for (int mi = 0; mi < 2; mi++) {
#pragma unroll
            for (int rr = 0; rr < 2; rr++) {
                const int r = mw * 32 + mi * 16 + rr * 8 + g;
                const int m = bx * 128 + r;
                const int b = m >> 9, t = m & 511;
                float* dst = g_xg + (((size_t)t * NCTA + cb) * BATCH + b) * 32 + gc0;
                dst[0] = acc[mi][ni][rr * 2]     + bv0;
                dst[1] = acc[mi][ni][rr * 2 + 1] + bv1;
            }
        }
    }
}

// ---------------- persistent recurrent kernel (fp16 1-term W, split-K) -----
// 128 CTAs x 512 threads (16 warps = 4K x 2M x 2N). 64KB W resident in SMEM.
// K=1024 as 2 x k512 A-stages. Warp (kw,mw,nw): m32 x n16 over its k128 slice
// per stage; 4 K-partials reduced via padded smem.
__global__ void __launch_bounds__(512, 1) lstm_persist(
    float* __restrict__ out, int write_final)
{
    extern __shared__ char smem[];
    float* sG4 = reinterpret_cast<float*>(smem + SM_A);   // [4][64][33] overlay on A stage 0

    const int tid  = threadIdx.x;
    const int warp = tid >> 5;
    const int lane = tid & 31;
    const int cb   = blockIdx.x;
    const int kw   = warp & 3;           // K slice (k128 per stage)
    const int mw   = (warp >> 2) & 1;    // M half (m32)
    const int nw   = warp >> 3;          // N half (n16)

    // resident W fragment preload (once): 64KB
    {
        const uint4* sh = reinterpret_cast<const uint4*>(g_Whf + (size_t)cb * WORDS_H);
        uint4* dh = reinterpret_cast<uint4*>(smem);
        for (int i = tid; i < WORDS_H / 4; i += 512) dh[i] = sh[i];
    }

    const int ui = tid & 7;
    const int bb = tid >> 3;             // 0..63 (also loader row)
    const int u  = cb * UPC + ui;
    float cst = 0.0f;

    const uint32_t sW_u = (uint32_t)__cvta_generic_to_shared(smem);
    const uint32_t sA_u = sW_u + SM_A;
    // ldmatrix base: row (lane&15), byte col = kw*256 + (lane>>4)*16
    const uint32_t abase0 = (uint32_t)((lane & 15) * A_STRIDE + kw * 256 + (lane >> 4) * 16);
    const int l_cc = tid & 7;            // loader: 8 threads x 8 chunks per row

    __syncthreads();

    for (int t = 0; t < SEQ; t++) {
        const int rb = t & 1, wb = rb ^ 1;
        float acc[2][2][4];
#pragma unroll
        for (int a = 0; a < 2; a++)
#pragma unroll
            for (int b = 0; b < 2; b++)
#pragma unroll
                for (int c = 0; c < 4; c++) acc[a][b][c] = 0.0f;

        // stage s covers k [s*512, s*512+512): 64 rows x 1024B; 4096 chunks,
        // thread (bb,l_cc) does 8 chunks at stride 128B.
        auto load_stage = [&](int s, int stage) {
            const __half* src = g_h[rb] + (size_t)bb * HSZ + s * 512 + l_cc * 8;
            const uint32_t dst = sA_u + stage * A_STG + bb * A_STRIDE + l_cc * 16;
#pragma unroll
            for (int j = 0; j < 8; j++)
                cp_async16_s(dst + j * 128, src + j * 64);
            cp_commit();
        };

        load_stage(0, 0);

        // xg prefetch (hides DRAM latency until epilogue)
        const float* xgp = g_xg + (((size_t)t * NCTA + cb) * BATCH + bb) * 32;
        float xg0 = xgp[ui];
        float xg1 = xgp[8 + ui];
        float xg2 = xgp[16 + ui];
        float xg3 = xgp[24 + ui];

#pragma unroll
        for (int s = 0; s < 2; s++) {
            asm volatile("cp.async.wait_group 0;\n" ::: "memory");
            __syncthreads();
            if (s == 0) load_stage(1, 1);

            const uint32_t Ab = sA_u + s * A_STG + abase0;
#pragma unroll
            for (int j = 0; j < 8; j++) {
                uint32_t a0[4], a1[4];
                LDSM4(a0, Ab + (mw * 32 + 0)  * A_STRIDE + j * 32);
                LDSM4(a1, Ab + (mw * 32 + 16) * A_STRIDE + j * 32);
                const int k16g = s * 32 + kw * 8 + j;
#pragma unroll
                for (int ni = 0; ni < 2; ni++) {
                    const int n8g = nw * 2 + ni;
                    const uint32_t Bb = sW_u + (uint32_t)((k16g * 4 + n8g) * 256 + lane * 8);
                    uint32_t b0, b1;
                    LDSV2(b0, b1, Bb);
                    MMA_F16(acc[0][ni], a0, b0, b1);
                    MMA_F16(acc[1][ni], a1, b0, b1);
                }
            }
        }

        // K-partial store into padded smem [4][64][33] (overlay on A stage 0;
        // free: all warps passed the s=1 top sync after their stage-0 reads).
        {
            const int g = lane >> 2, t4 = lane & 3;
#pragma unroll
            for (int mi = 0; mi < 2; mi++)
#pragma unroll
                for (int ni = 0; ni < 2; ni++) {
                    const int r = mw * 32 + mi * 16 + g;
                    const int c = (nw * 2 + ni) * 8 + t4 * 2;
                    float* p = sG4 + (kw * 64 + r) * 33 + c;
                    p[0]          = acc[mi][ni][0];
                    p[1]          = acc[mi][ni][1];
                    p[8 * 33]     = acc[mi][ni][2];
                    p[8 * 33 + 1] = acc[mi][ni][3];
                }
        }
        __syncthreads();

        // reduce 4 K-partials + cell update: thread owns (bb, ui)
        {
            float gf = 0.f, gi = 0.f, gc = 0.f, go = 0.f;
#pragma unroll
            for (int k = 0; k < 4; k++) {
                const float* p = sG4 + (k * 64 + bb) * 33;
                gf += p[ui];
                gi += p[8 + ui];
                gc += p[16 + ui];
                go += p[24 + ui];
            }
            float fg = sigmoidf_(gf + xg0);
            float ig = sigmoidf_(gi + xg1);
            float cg = tanhf    (gc + xg2);
            float og = sigmoidf_(go + xg3);
            cst = fg * cst + ig * cg;
            float h = og * tanhf(cst);
            out[((size_t)bb * SEQ + t) * HSZ + u] = h;
            g_h[wb][bb * HSZ + u] = __float2half_rn(h);
            if (t == SEQ - 1 && write_final) {
                out[(size_t)BATCH * SEQ * HSZ + bb * HSZ + u]               = h;
                out[(size_t)BATCH * SEQ * HSZ + BATCH * HSZ + bb * HSZ + u] = cst;
            }
        }

        // flag-array grid barrier
        __syncthreads();
        if (tid == 0) {
            __threadfence();
            asm volatile("st.relaxed.gpu.u32 [%0], %1;"
                         :: "l"(g_flags + cb * 32), "r"((unsigned)(t + 1)) : "memory");
        }
        if (tid < NCTA) {
            const unsigned* fl = (const unsigned*)(g_flags + tid * 32);
            unsigned v;
            do {
                asm volatile("ld.acquire.gpu.u32 %0, [%1];" : "=r"(v) : "l"(fl) : "memory");
            } while (v < (unsigned)(t + 1));
        }
        __syncthreads();
    }
}

// ---------------- launch ----------------
extern "C" void kernel_launch(void* const* d_in, const int* in_sizes, int n_in,
                              void* d_out, int out_size) {
    const float* x = nullptr;
    const float* W = nullptr;
    const float* bias = nullptr;
    for (int i = 0; i < n_in; i++) {
        if (in_sizes[i] == BATCH * SEQ * ISZ)           x = (const float*)d_in[i];
        else if (in_sizes[i] == (ISZ + HSZ) * GSZ)      W = (const float*)d_in[i];
        else if (in_sizes[i] == GSZ)                    bias = (const float*)d_in[i];
    }
    float* out = (float*)d_out;
    const long long full = (long long)BATCH * SEQ * HSZ + 2LL * BATCH * HSZ;
    const int write_final = (out_size >= full) ? 1 : 0;

    cudaFuncSetAttribute(lstm_persist, cudaFuncAttributeMaxDynamicSharedMemorySize, SMEM_TOTAL);
    cudaFuncSetAttribute(xw_gemm, cudaFuncAttributeMaxDynamicSharedMemorySize, XG_SMEM);

    {
        int n4 = BATCH * SEQ * ISZ / 4;
        prep_x<<<(n4 + 255) / 256, 256>>>(x);
    }
    {
        long long n = (long long)NCTA * WORDS_H;
        prep_wh<<<(unsigned)((n + 255) / 256), 256>>>(W);
    }
    {
        long long n = (long long)NCTA * WORDS_X;
        prep_wx<<<(unsigned)((n + 255) / 256), 256>>>(W);
    }
    prep_state<<<(2 * BATCH * HSZ + 255) / 256, 256>>>();

    {
        dim3 grid(SEQ * BATCH / 128, NCTA / CBQ);
        xw_gemm<<<grid, 256, XG_SMEM>>>(bias);
    }

    lstm_persist<<<NCTA, 512, SMEM_TOTAL>>>(out, write_final);
}

// round 9
// speedup vs baseline: 5.4636x; 1.2351x over previous
#include <cuda_runtime.h>
#include <cuda_bf16.h>
#include <cuda_fp16.h>
#include <cstdint>

// ---------------- problem dims ----------------
#define BATCH 64
#define SEQ   512
#define ISZ   512
#define HSZ   1024
#define GSZ   4096
#define NCTA  128            // persistent CTAs
#define UPC   8              // hidden units per CTA (32 gate cols)
#define WORDS_H (64 * 4 * 32 * 2)      // 16384 u32 (half2 frags) per CTA (1 term)
#define NK16X 32             // k16 tiles for x GEMM (K=512, 1 term)
#define WORDS_X (NK16X * 4 * 32 * 2)   // 8192 u32 per CTA-col-block
#define CBQ   4              // cb blocks per xw CTA
#define NKTX  16             // k32 tiles in x GEMM

// recurrent smem layout (bytes): W 64KB, then 2 A stages of k512
#define SM_A     65536
#define A_STRIDE 1040                   // 1024B data + 16B pad
#define A_STG    (64 * A_STRIDE)        // 66560 per stage
#define SMEM_TOTAL (SM_A + 2 * A_STG)   // 198656

// xw smem (dynamic): 3 stages A + 3 stages B
#define XG_A_STAGE 10240     // 128 rows x 80B (fp16 k32)
#define XG_B_STAGE 8192      // 4 cb x 2KB
#define XG_SMEM (3 * (XG_A_STAGE + XG_B_STAGE))   // 55296

// ---------------- persistent device scratch ----------------
__device__ __align__(256) unsigned g_Whf[(size_t)NCTA * WORDS_H];     // 8 MB (fp16 pairs)
__device__ __align__(256) unsigned g_Wxf[(size_t)NCTA * WORDS_X];     // 4.2 MB (fp16 pairs)
__device__ __align__(256) __half   g_xh[(size_t)BATCH * SEQ * ISZ];   // 32 MB fp16 x
__device__ __align__(256) __half   g_xg[(size_t)SEQ * NCTA * BATCH * 32]; // 256 MB fp16 xg
__device__ __align__(256) __half   g_h[2][BATCH * HSZ];               // fp16 h, ping-pong
__device__ __align__(128) unsigned g_flags[NCTA * 32];

// ---------------- helpers ----------------
__device__ __forceinline__ void cp_async16_s(uint32_t dst_smem, const void* src) {
    asm volatile("cp.async.cg.shared.global [%0], [%1], 16;\n"
                 :: "r"(dst_smem), "l"(src) : "memory");
}
__device__ __forceinline__ void cp_commit() {
    asm volatile("cp.async.commit_group;\n" ::: "memory");
}
__device__ __forceinline__ float sigmoidf_(float v) { return 1.0f / (1.0f + expf(-v)); }

#define LDSM4(R, ADDR) \
    asm volatile("ldmatrix.sync.aligned.m8n8.x4.shared.b16 {%0,%1,%2,%3},[%4];" \
                 : "=r"((R)[0]), "=r"((R)[1]), "=r"((R)[2]), "=r"((R)[3]) : "r"(ADDR))

#define MMA_F16(ACC, A, B0, B1) \
    asm volatile("mma.sync.aligned.m16n8k16.row.col.f32.f16.f16.f32 " \
                 "{%0,%1,%2,%3},{%4,%5,%6,%7},{%8,%9},{%0,%1,%2,%3};" \
                 : "+f"((ACC)[0]), "+f"((ACC)[1]), "+f"((ACC)[2]), "+f"((ACC)[3]) \
                 : "r"((A)[0]), "r"((A)[1]), "r"((A)[2]), "r"((A)[3]), "r"(B0), "r"(B1))

#define LDSV2(R0, R1, ADDR) \
    asm volatile("ld.shared.v2.u32 {%0,%1},[%2];" : "=r"(R0), "=r"(R1) : "r"(ADDR))

// ---------------- prep kernels ----------------
__global__ void prep_x(const float* __restrict__ x) {
    size_t i = (size_t)blockIdx.x * blockDim.x + threadIdx.x;
    size_t n4 = (size_t)BATCH * SEQ * ISZ / 4;
    if (i >= n4) return;
    float4 v = reinterpret_cast<const float4*>(x)[i];
    __half2* d = reinterpret_cast<__half2*>(g_xh);
    d[i * 2]     = __halves2half2(__float2half_rn(v.x), __float2half_rn(v.y));
    d[i * 2 + 1] = __halves2half2(__float2half_rn(v.z), __float2half_rn(v.w));
}

// Wh fragments in fp16, single term (K=1024, rows ISZ.. of W).
__global__ void prep_wh(const float* __restrict__ W) {
    size_t w = (size_t)blockIdx.x * blockDim.x + threadIdx.x;
    if (w >= (size_t)NCTA * WORDS_H) return;
    int q    = (int)(w & 1);
    int lane = (int)((w >> 1) & 31);
    int n8   = (int)((w >> 6) & 3);
    int k16  = (int)((w >> 8) & 63);
    int cb   = (int)(w >> 14);
    int k  = k16 * 16 + (lane & 3) * 2 + q * 8;
    int nl = n8 * 8 + (lane >> 2);
    int col = (nl >> 3) * HSZ + cb * UPC + (nl & 7);
    __half h0 = __float2half_rn(W[(size_t)(ISZ + k) * GSZ + col]);
    __half h1 = __float2half_rn(W[(size_t)(ISZ + k + 1) * GSZ + col]);
    __half2 ph = __halves2half2(h0, h1);
    g_Whf[w] = *reinterpret_cast<unsigned*>(&ph);
}

// Wx fragments in fp16, single term (K=512, rows 0..511 of W).
// word w = (((cb*32 + k16)*4 + n8)*32 + lane)*2 + q
__global__ void prep_wx(const float* __restrict__ W) {
    size_t w = (size_t)blockIdx.x * blockDim.x + threadIdx.x;
    if (w >= (size_t)NCTA * WORDS_X) return;
    int q    = (int)(w & 1);
    int lane = (int)((w >> 1) & 31);
    int n8   = (int)((w >> 6) & 3);
    int k16  = (int)((w >> 8) & 31);
    int cb   = (int)(w >> 13);
    int k  = k16 * 16 + (lane & 3) * 2 + q * 8;
    int nl = n8 * 8 + (lane >> 2);
    int col = (nl >> 3) * HSZ + cb * UPC + (nl & 7);
    __half h0 = __float2half_rn(W[(size_t)k * GSZ + col]);
    __half h1 = __float2half_rn(W[(size_t)(k + 1) * GSZ + col]);
    __half2 ph = __halves2half2(h0, h1);
    g_Wxf[w] = *reinterpret_cast<unsigned*>(&ph);
}

__global__ void prep_state() {
    int i = blockIdx.x * blockDim.x + threadIdx.x;
    if (i < 2 * BATCH * HSZ) (&g_h[0][0])[i] = __float2half(0.0f);
    if (i < NCTA * 32) g_flags[i] = 0u;
}

// ---------------- xg precompute GEMM (fp16 1-term, K=512) ----------------
// grid (SEQ*BATCH/128 = 256 m-tiles, NCTA/CBQ = 32), 256 threads.
// Each CTA: M=128 tokens, N=128 (4 cb blocks), K=512, 16 k32 tiles.
__global__ void __launch_bounds__(256) xw_gemm(const float* __restrict__ bias) {
    extern __shared__ char smem[];
    const uint32_t sA_u = (uint32_t)__cvta_generic_to_shared(smem);
    const uint32_t sB_u = sA_u + 3 * XG_A_STAGE;

    const int tid  = threadIdx.x;
    const int warp = tid >> 5;
    const int lane = tid & 31;
    const int bx   = blockIdx.x;
    const int cb0  = blockIdx.y * CBQ;
    const int mw   = warp >> 1;      // 4 M-warps (32 rows each)
    const int nw   = warp & 1;       // 2 N-warps (64 cols each)

    float acc[2][8][4];
#pragma unroll
    for (int a = 0; a < 2; a++)
#pragma unroll
        for (int b = 0; b < 8; b++)
#pragma unroll
            for (int c = 0; c < 4; c++) acc[a][b][c] = 0.0f;

    auto load_tile = [&](int kt, int stage) {
        const int k0 = kt * 32;
        // A: 128 rows x 32 k (64B) = 512 chunks
#pragma unroll
        for (int j = 0; j < 2; j++) {
            int ch = tid + j * 256;
            int rr = ch >> 2, cc = ch & 3;
            cp_async16_s(sA_u + stage * XG_A_STAGE + rr * 80 + cc * 16,
                         g_xh + ((size_t)(bx * 128 + rr)) * ISZ + k0 + cc * 8);
        }
        // B: 4 cb x 512 words = 512 chunks
#pragma unroll
        for (int j = 0; j < 2; j++) {
            int ch = tid + j * 256;
            int q = ch >> 7, ww = ch & 127;
            const unsigned* src = g_Wxf + ((size_t)(cb0 + q) * NK16X + kt * 2) * 256 + ww * 4;
            cp_async16_s(sB_u + stage * XG_B_STAGE + q * 2048 + ww * 16, src);
        }
        cp_commit();
    };

    load_tile(0, 0);
    load_tile(1, 1);

    const uint32_t arow = (uint32_t)((mw * 32 + (lane & 15)) * 80 + (lane >> 4) * 16);

#pragma unroll
    for (int kt = 0; kt < NKTX; kt++) {
        if (kt == NKTX - 1) { asm volatile("cp.async.wait_group 0;\n" ::: "memory"); }
        else                { asm volatile("cp.async.wait_group 1;\n" ::: "memory"); }
        __syncthreads();
        if (kt + 2 < NKTX) load_tile(kt + 2, (kt + 2) % 3);

        const int stage = kt % 3;
        const uint32_t Ab = sA_u + stage * XG_A_STAGE + arow;
        const uint32_t Bb = sB_u + stage * XG_B_STAGE + lane * 8;
#pragma unroll
        for (int sub = 0; sub < 2; sub++) {
            uint32_t a0[4], a1[4];
            LDSM4(a0, Ab + sub * 32);
            LDSM4(a1, Ab + 16 * 80 + sub * 32);
#pragma unroll
            for (int ni = 0; ni < 8; ni++) {
                const int q = nw * 2 + (ni >> 2);
                const int n8l = ni & 3;
                uint32_t b0, b1;
                LDSV2(b0, b1, Bb + q * 2048 + (sub * 4 + n8l) * 256);
                MMA_F16(acc[0][ni], a0, b0, b1);
                MMA_F16(acc[1][ni], a1, b0, b1);
            }
        }
    }

    // epilogue: pack (acc + bias) into fp16 pairs, store into permuted xg
    const int g = lane >> 2, t4 = lane & 3;
#pragma unroll
    for (int ni = 0; ni < 8; ni++) {
        const int q   = nw * 2 + (ni >> 2);
        const int cb  = cb0 + q;
        const int gc0 = (ni & 3) * 8 + t4 * 2;
        const float bv0 = bias[(gc0 >> 3) * HSZ + cb * UPC + (gc0 & 7)];
        const float bv1 = bias[(gc0 >> 3) * HSZ + cb * UPC + (gc0 & 7) + 1];
#pragma unroll
        for (int mi = 0; mi < 2; mi++) {
#pragma unroll
            for (int rr = 0; rr < 2; rr++) {
                const int r = mw * 32 + mi * 16 + rr * 8 + g;
                const int m = bx * 128 + r;
                const int b = m >> 9, t = m & 511;
                __half2 pv = __halves2half2(
                    __float2half_rn(acc[mi][ni][rr * 2]     + bv0),
                    __float2half_rn(acc[mi][ni][rr * 2 + 1] + bv1));
                __half2* dst = reinterpret_cast<__half2*>(
                    g_xg + (((size_t)t * NCTA + cb) * BATCH + b) * 32 + gc0);
                *dst = pv;
            }
        }
    }
}

// ---------------- persistent recurrent kernel (fp16 1-term W, split-K) -----
// 128 CTAs x 512 threads (16 warps = 4K x 2M x 2N). 64KB W resident in SMEM.
__global__ void __launch_bounds__(512, 1) lstm_persist(
    float* __restrict__ out, int write_final)
{
    extern __shared__ char smem[];
    float* sG4 = reinterpret_cast<float*>(smem + SM_A);   // [4][64][33] overlay on A stage 0

    const int tid  = threadIdx.x;
    const int warp = tid >> 5;
    const int lane = tid & 31;
    const int cb   = blockIdx.x;
    const int kw   = warp & 3;           // K slice (k128 per stage)
    const int mw   = (warp >> 2) & 1;    // M half (m32)
    const int nw   = warp >> 3;          // N half (n16)

    // resident W fragment preload (once): 64KB
    {
        const uint4* sh = reinterpret_cast<const uint4*>(g_Whf + (size_t)cb * WORDS_H);
        uint4* dh = reinterpret_cast<uint4*>(smem);
        for (int i = tid; i < WORDS_H / 4; i += 512) dh[i] = sh[i];
    }

    const int ui = tid & 7;
    const int bb = tid >> 3;             // 0..63 (also loader row)
    const int u  = cb * UPC + ui;
    float cst = 0.0f;

    const uint32_t sW_u = (uint32_t)__cvta_generic_to_shared(smem);
    const uint32_t sA_u = sW_u + SM_A;
    const uint32_t abase0 = (uint32_t)((lane & 15) * A_STRIDE + kw * 256 + (lane >> 4) * 16);
    const int l_cc = tid & 7;

    __syncthreads();

    for (int t = 0; t < SEQ; t++) {
        const int rb = t & 1, wb = rb ^ 1;
        float acc[2][2][4];
#pragma unroll
        for (int a = 0; a < 2; a++)
#pragma unroll
            for (int b = 0; b < 2; b++)
#pragma unroll
                for (int c = 0; c < 4; c++) acc[a][b][c] = 0.0f;

        auto load_stage = [&](int s, int stage) {
            const __half* src = g_h[rb] + (size_t)bb * HSZ + s * 512 + l_cc * 8;
            const uint32_t dst = sA_u + stage * A_STG + bb * A_STRIDE + l_cc * 16;
#pragma unroll
            for (int j = 0; j < 8; j++)
                cp_async16_s(dst + j * 128, src + j * 64);
            cp_commit();
        };

        load_stage(0, 0);

        // xg prefetch (fp16; hides DRAM latency until epilogue)
        const __half* xgp = g_xg + (((size_t)t * NCTA + cb) * BATCH + bb) * 32;
        float xg0 = __half2float(xgp[ui]);
        float xg1 = __half2float(xgp[8 + ui]);
        float xg2 = __half2float(xgp[16 + ui]);
        float xg3 = __half2float(xgp[24 + ui]);

#pragma unroll
        for (int s = 0; s < 2; s++) {
            asm volatile("cp.async.wait_group 0;\n" ::: "memory");
            __syncthreads();
            if (s == 0) load_stage(1, 1);

            const uint32_t Ab = sA_u + s * A_STG + abase0;
#pragma unroll
            for (int j = 0; j < 8; j++) {
                uint32_t a0[4], a1[4];
                LDSM4(a0, Ab + (mw * 32 + 0)  * A_STRIDE + j * 32);
                LDSM4(a1, Ab + (mw * 32 + 16) * A_STRIDE + j * 32);
                const int k16g = s * 32 + kw * 8 + j;
#pragma unroll
                for (int ni = 0; ni < 2; ni++) {
                    const int n8g = nw * 2 + ni;
                    const uint32_t Bb = sW_u + (uint32_t)((k16g * 4 + n8g) * 256 + lane * 8);
                    uint32_t b0, b1;
                    LDSV2(b0, b1, Bb);
                    MMA_F16(acc[0][ni], a0, b0, b1);
                    MMA_F16(acc[1][ni], a1, b0, b1);
                }
            }
        }

        // K-partial store into padded smem [4][64][33]
        {
            const int g = lane >> 2, t4 = lane & 3;
#pragma unroll
            for (int mi = 0; mi < 2; mi++)
#pragma unroll
                for (int ni = 0; ni < 2; ni++) {
                    const int r = mw * 32 + mi * 16 + g;
                    const int c = (nw * 2 + ni) * 8 + t4 * 2;
                    float* p = sG4 + (kw * 64 + r) * 33 + c;
                    p[0]          = acc[mi][ni][0];
                    p[1]          = acc[mi][ni][1];
                    p[8 * 33]     = acc[mi][ni][2];
                    p[8 * 33 + 1] = acc[mi][ni][3];
                }
        }
        __syncthreads();

        // reduce 4 K-partials + cell update: thread owns (bb, ui)
        {
            float gf = 0.f, gi = 0.f, gc = 0.f, go = 0.f;
#pragma unroll
            for (int k = 0; k < 4; k++) {
                const float* p = sG4 + (k * 64 + bb) * 33;
                gf += p[ui];
                gi += p[8 + ui];
                gc += p[16 + ui];
                go += p[24 + ui];
            }
            float fg = sigmoidf_(gf + xg0);
            float ig = sigmoidf_(gi + xg1);
            float cg = tanhf    (gc + xg2);
            float og = sigmoidf_(go + xg3);
            cst = fg * cst + ig * cg;
            float h = og * tanhf(cst);
            out[((size_t)bb * SEQ + t) * HSZ + u] = h;
            g_h[wb][bb * HSZ + u] = __float2half_rn(h);
            if (t == SEQ - 1 && write_final) {
                out[(size_t)BATCH * SEQ * HSZ + bb * HSZ + u]               = h;
                out[(size_t)BATCH * SEQ * HSZ + BATCH * HSZ + bb * HSZ + u] = cst;
            }
        }

        // flag-array grid barrier
        __syncthreads();
        if (tid == 0) {
            __threadfence();
            asm volatile("st.relaxed.gpu.u32 [%0], %1;"
                         :: "l"(g_flags + cb * 32), "r"((unsigned)(t + 1)) : "memory");
        }
        if (tid < NCTA) {
            const unsigned* fl = (const unsigned*)(g_flags + tid * 32);
            unsigned v;
            do {
                asm volatile("ld.acquire.gpu.u32 %0, [%1];" : "=r"(v) : "l"(fl) : "memory");
            } while (v < (unsigned)(t + 1));
        }
        __syncthreads();
    }
}

// ---------------- launch ----------------
extern "C" void kernel_launch(void* const* d_in, const int* in_sizes, int n_in,
                              void* d_out, int out_size) {
    const float* x = nullptr;
    const float* W = nullptr;
    const float* bias = nullptr;
    for (int i = 0; i < n_in; i++) {
        if (in_sizes[i] == BATCH * SEQ * ISZ)           x = (const float*)d_in[i];
        else if (in_sizes[i] == (ISZ + HSZ) * GSZ)      W = (const float*)d_in[i];
        else if (in_sizes[i] == GSZ)                    bias = (const float*)d_in[i];
    }
    float* out = (float*)d_out;
    const long long full = (long long)BATCH * SEQ * HSZ + 2LL * BATCH * HSZ;
    const int write_final = (out_size >= full) ? 1 : 0;

    cudaFuncSetAttribute(lstm_persist, cudaFuncAttributeMaxDynamicSharedMemorySize, SMEM_TOTAL);
    cudaFuncSetAttribute(xw_gemm, cudaFuncAttributeMaxDynamicSharedMemorySize, XG_SMEM);

    {
        int n4 = BATCH * SEQ * ISZ / 4;
        prep_x<<<(n4 + 255) / 256, 256>>>(x);
    }
    {
        long long n = (long long)NCTA * WORDS_H;
        prep_wh<<<(unsigned)((n + 255) / 256), 256>>>(W);
    }
    {
        long long n = (long long)NCTA * WORDS_X;
        prep_wx<<<(unsigned)((n + 255) / 256), 256>>>(W);
    }
    prep_state<<<(2 * BATCH * HSZ + 255) / 256, 256>>>();

    {
        dim3 grid(SEQ * BATCH / 128, NCTA / CBQ);
        xw_gemm<<<grid, 256, XG_SMEM>>>(bias);
    }

    lstm_persist<<<NCTA, 512, SMEM_TOTAL>>>(out, write_final);
}

// round 10
// speedup vs baseline: 6.7268x; 1.2312x over previous
#include <cuda_runtime.h>
#include <cuda_bf16.h>
#include <cuda_fp16.h>
#include <cstdint>

// ---------------- problem dims ----------------
#define BATCH 64
#define SEQ   512
#define ISZ   512
#define HSZ   1024
#define GSZ   4096
#define NCTA  128            // 2 batch-groups x 64 column-groups
#define NCG   64             // column groups
#define UPC   16             // hidden units per cg (64 gate cols)
#define MB    32             // batches per CTA
#define WORDS_H (64 * 8 * 32 * 2)      // 32768 u32 per cg (fp16 frags, K=1024, N=64)
#define WORDS_X (32 * 8 * 32 * 2)      // 16384 u32 per cg (K=512, N=64)
#define CBQ   2              // cg blocks per xw CTA
#define NKTX  16             // k32 tiles in x GEMM

// recurrent smem layout (bytes): W 128KB, then 2 A stages (32 rows x k512)
#define SM_A     131072
#define A_STRIDE 1040                   // 1024B data + 16B pad
#define A_STG    (32 * A_STRIDE)        // 33280 per stage
#define SMEM_TOTAL (SM_A + 2 * A_STG)   // 197632
// gate-partial overlay on A stage 0: [4][32][65] floats = 33280 B exactly
#define SG_PLANE 2080                   // 32*65 floats per kw plane

// xw smem (dynamic): 3 stages A + 3 stages B
#define XG_A_STAGE 10240     // 128 rows x 80B (fp16 k32)
#define XG_B_STAGE 8192      // 2 cg x 4KB
#define XG_SMEM (3 * (XG_A_STAGE + XG_B_STAGE))   // 55296

// ---------------- persistent device scratch ----------------
__device__ __align__(256) unsigned g_Whf[(size_t)NCG * WORDS_H];      // 8 MB
__device__ __align__(256) unsigned g_Wxf[(size_t)NCG * WORDS_X];      // 4 MB
__device__ __align__(256) __half   g_xh[(size_t)BATCH * SEQ * ISZ];   // 32 MB
__device__ __align__(256) __half   g_xg[(size_t)SEQ * NCG * BATCH * 64]; // 256 MB
__device__ __align__(256) __half   g_h[2][BATCH * HSZ];               // fp16 h, ping-pong
__device__ __align__(128) unsigned g_flags[NCTA * 32];

// ---------------- helpers ----------------
__device__ __forceinline__ void cp_async16_s(uint32_t dst_smem, const void* src) {
    asm volatile("cp.async.cg.shared.global [%0], [%1], 16;\n"
                 :: "r"(dst_smem), "l"(src) : "memory");
}
__device__ __forceinline__ void cp_commit() {
    asm volatile("cp.async.commit_group;\n" ::: "memory");
}
__device__ __forceinline__ float sigmoidf_(float v) { return 1.0f / (1.0f + expf(-v)); }

#define LDSM4(R, ADDR) \
    asm volatile("ldmatrix.sync.aligned.m8n8.x4.shared.b16 {%0,%1,%2,%3},[%4];" \
                 : "=r"((R)[0]), "=r"((R)[1]), "=r"((R)[2]), "=r"((R)[3]) : "r"(ADDR))

#define MMA_F16(ACC, A, B0, B1) \
    asm volatile("mma.sync.aligned.m16n8k16.row.col.f32.f16.f16.f32 " \
                 "{%0,%1,%2,%3},{%4,%5,%6,%7},{%8,%9},{%0,%1,%2,%3};" \
                 : "+f"((ACC)[0]), "+f"((ACC)[1]), "+f"((ACC)[2]), "+f"((ACC)[3]) \
                 : "r"((A)[0]), "r"((A)[1]), "r"((A)[2]), "r"((A)[3]), "r"(B0), "r"(B1))

#define LDSV2(R0, R1, ADDR) \
    asm volatile("ld.shared.v2.u32 {%0,%1},[%2];" : "=r"(R0), "=r"(R1) : "r"(ADDR))

// ---------------- prep kernels ----------------
__global__ void prep_x(const float* __restrict__ x) {
    size_t i = (size_t)blockIdx.x * blockDim.x + threadIdx.x;
    size_t n4 = (size_t)BATCH * SEQ * ISZ / 4;
    if (i >= n4) return;
    float4 v = reinterpret_cast<const float4*>(x)[i];
    __half2* d = reinterpret_cast<__half2*>(g_xh);
    d[i * 2]     = __halves2half2(__float2half_rn(v.x), __float2half_rn(v.y));
    d[i * 2 + 1] = __halves2half2(__float2half_rn(v.z), __float2half_rn(v.w));
}

// Wh fragments fp16 (K=1024, N=64 per cg).
// word w = (((cg*64 + k16)*8 + n8)*32 + lane)*2 + q holds {B[k][n],B[k+1][n]}.
// local col nl = n8*8 + lane/4 = gate*16 + ui; W col = gate*HSZ + cg*16 + ui.
__global__ void prep_wh(const float* __restrict__ W) {
    size_t w = (size_t)blockIdx.x * blockDim.x + threadIdx.x;
    if (w >= (size_t)NCG * WORDS_H) return;
    int q    = (int)(w & 1);
    int lane = (int)((w >> 1) & 31);
    int n8   = (int)((w >> 6) & 7);
    int k16  = (int)((w >> 9) & 63);
    int cg   = (int)(w >> 15);
    int k  = k16 * 16 + (lane & 3) * 2 + q * 8;
    int nl = n8 * 8 + (lane >> 2);
    int col = (nl >> 4) * HSZ + cg * UPC + (nl & 15);
    __half h0 = __float2half_rn(W[(size_t)(ISZ + k) * GSZ + col]);
    __half h1 = __float2half_rn(W[(size_t)(ISZ + k + 1) * GSZ + col]);
    __half2 ph = __halves2half2(h0, h1);
    g_Whf[w] = *reinterpret_cast<unsigned*>(&ph);
}

// Wx fragments fp16 (K=512, N=64 per cg).
__global__ void prep_wx(const float* __restrict__ W) {
    size_t w = (size_t)blockIdx.x * blockDim.x + threadIdx.x;
    if (w >= (size_t)NCG * WORDS_X) return;
    int q    = (int)(w & 1);
    int lane = (int)((w >> 1) & 31);
    int n8   = (int)((w >> 6) & 7);
    int k16  = (int)((w >> 9) & 31);
    int cg   = (int)(w >> 14);
    int k  = k16 * 16 + (lane & 3) * 2 + q * 8;
    int nl = n8 * 8 + (lane >> 2);
    int col = (nl >> 4) * HSZ + cg * UPC + (nl & 15);
    __half h0 = __float2half_rn(W[(size_t)k * GSZ + col]);
    __half h1 = __float2half_rn(W[(size_t)(k + 1) * GSZ + col]);
    __half2 ph = __halves2half2(h0, h1);
    g_Wxf[w] = *reinterpret_cast<unsigned*>(&ph);
}

__global__ void prep_state() {
    int i = blockIdx.x * blockDim.x + threadIdx.x;
    if (i < 2 * BATCH * HSZ) (&g_h[0][0])[i] = __float2half(0.0f);
    if (i < NCTA * 32) g_flags[i] = 0u;
}

// ---------------- xg precompute GEMM (fp16, K=512) ----------------
// grid (256 m-tiles, 32 cg-pairs), 256 threads (8 warps = 4M x 2N).
// CTA: M=128 tokens, N=128 (2 cg x 64 cols), K=512.
__global__ void __launch_bounds__(256) xw_gemm(const float* __restrict__ bias) {
    extern __shared__ char smem[];
    const uint32_t sA_u = (uint32_t)__cvta_generic_to_shared(smem);
    const uint32_t sB_u = sA_u + 3 * XG_A_STAGE;

    const int tid  = threadIdx.x;
    const int warp = tid >> 5;
    const int lane = tid & 31;
    const int bx   = blockIdx.x;
    const int cg0  = blockIdx.y * CBQ;
    const int mw   = warp >> 1;      // 4 M-warps (32 rows each)
    const int nw   = warp & 1;       // cg select (64 cols each)

    float acc[2][8][4];
#pragma unroll
    for (int a = 0; a < 2; a++)
#pragma unroll
        for (int b = 0; b < 8; b++)
#pragma unroll
            for (int c = 0; c < 4; c++) acc[a][b][c] = 0.0f;

    auto load_tile = [&](int kt, int stage) {
        const int k0 = kt * 32;
        // A: 128 rows x 32 k (64B) = 512 chunks
#pragma unroll
        for (int j = 0; j < 2; j++) {
            int ch = tid + j * 256;
            int rr = ch >> 2, cc = ch & 3;
            cp_async16_s(sA_u + stage * XG_A_STAGE + rr * 80 + cc * 16,
                         g_xh + ((size_t)(bx * 128 + rr)) * ISZ + k0 + cc * 8);
        }
        // B: 2 cg x 4KB = 512 chunks
#pragma unroll
        for (int j = 0; j < 2; j++) {
            int ch = tid + j * 256;
            int q = ch >> 8, ww = ch & 255;
            const unsigned* src = g_Wxf + (size_t)(cg0 + q) * WORDS_X + kt * 1024 + ww * 4;
            cp_async16_s(sB_u + stage * XG_B_STAGE + q * 4096 + ww * 16, src);
        }
        cp_commit();
    };

    load_tile(0, 0);
    load_tile(1, 1);

    const uint32_t arow = (uint32_t)((mw * 32 + (lane & 15)) * 80 + (lane >> 4) * 16);

#pragma unroll
    for (int kt = 0; kt < NKTX; kt++) {
        if (kt == NKTX - 1) { asm volatile("cp.async.wait_group 0;\n" ::: "memory"); }
        else                { asm volatile("cp.async.wait_group 1;\n" ::: "memory"); }
        __syncthreads();
        if (kt + 2 < NKTX) load_tile(kt + 2, (kt + 2) % 3);

        const int stage = kt % 3;
        const uint32_t Ab = sA_u + stage * XG_A_STAGE + arow;
        const uint32_t Bb = sB_u + stage * XG_B_STAGE + nw * 4096 + lane * 8;
#pragma unroll
        for (int sub = 0; sub < 2; sub++) {
            uint32_t a0[4], a1[4];
            LDSM4(a0, Ab + sub * 32);
            LDSM4(a1, Ab + 16 * 80 + sub * 32);
#pragma unroll
            for (int ni = 0; ni < 8; ni++) {
                uint32_t b0, b1;
                LDSV2(b0, b1, Bb + (sub * 8 + ni) * 256);
                MMA_F16(acc[0][ni], a0, b0, b1);
                MMA_F16(acc[1][ni], a1, b0, b1);
            }
        }
    }

    // epilogue: pack (acc + bias) into fp16 pairs, store into permuted xg
    const int g = lane >> 2, t4 = lane & 3;
    const int cg = cg0 + nw;
#pragma unroll
    for (int ni = 0; ni < 8; ni++) {
        const int gc0 = ni * 8 + t4 * 2;          // local col 0..63 = gate*16+ui
        const int gate = gc0 >> 4, ui = gc0 & 15;
        const float bv0 = bias[gate * HSZ + cg * UPC + ui];
        const float bv1 = bias[gate * HSZ + cg * UPC + ui + 1];
#pragma unroll
        for (int mi = 0; mi < 2; mi++) {
#pragma unroll
            for (int rr = 0; rr < 2; rr++) {
                const int r = mw * 32 + mi * 16 + rr * 8 + g;
                const int m = bx * 128 + r;
                const int b = m >> 9, t = m & 511;
                __half2 pv = __halves2half2(
                    __float2half_rn(acc[mi][ni][rr * 2]     + bv0),
                    __float2half_rn(acc[mi][ni][rr * 2 + 1] + bv1));
                __half2* dst = reinterpret_cast<__half2*>(
                    g_xg + (((size_t)t * NCG + cg) * BATCH + b) * 64 + gc0);
                *dst = pv;
            }
        }
    }
}

// ---------------- persistent recurrent kernel ----------------
// 128 CTAs x 256 threads (8 warps = 4K x 2N). CTA (bg,cg): 32 batches x 64
// gate cols, K=1024. 128KB W resident in SMEM; 2 x k512 A stages.
__global__ void __launch_bounds__(256, 1) lstm_persist(
    float* __restrict__ out, int write_final)
{
    extern __shared__ char smem[];
    float* sG4 = reinterpret_cast<float*>(smem + SM_A);   // [4][32][65] overlay

    const int tid  = threadIdx.x;
    const int warp = tid >> 5;
    const int lane = tid & 31;
    const int cb   = blockIdx.x;
    const int cg   = cb & 63;
    const int bg   = cb >> 6;
    const int kw   = warp & 3;           // K slice (k128 per stage)
    const int nw   = warp >> 2;          // N half (n32)

    // resident W fragment preload (once): 128KB
    {
        const uint4* sh = reinterpret_cast<const uint4*>(g_Whf + (size_t)cg * WORDS_H);
        uint4* dh = reinterpret_cast<uint4*>(smem);
        for (int i = tid; i < WORDS_H / 4; i += 256) dh[i] = sh[i];
    }

    float cst0 = 0.0f, cst1 = 0.0f;

    const uint32_t sW_u = (uint32_t)__cvta_generic_to_shared(smem);
    const uint32_t sA_u = sW_u + SM_A;
    const uint32_t abase = (uint32_t)((lane & 15) * A_STRIDE + kw * 256 + (lane >> 4) * 16);
    const int l_row = tid >> 3;          // 0..31
    const int l_cc  = tid & 7;           // 0..7

    __syncthreads();

    for (int t = 0; t < SEQ; t++) {
        const int rb = t & 1, wb = rb ^ 1;
        float acc[2][4][4];
#pragma unroll
        for (int a = 0; a < 2; a++)
#pragma unroll
            for (int b = 0; b < 4; b++)
#pragma unroll
                for (int c = 0; c < 4; c++) acc[a][b][c] = 0.0f;

        auto load_stage = [&](int s, int stage) {
            const __half* src = g_h[rb] + (size_t)(bg * MB + l_row) * HSZ + s * 512 + l_cc * 8;
            const uint32_t dst = sA_u + stage * A_STG + l_row * A_STRIDE + l_cc * 16;
#pragma unroll
            for (int j = 0; j < 8; j++)
                cp_async16_s(dst + j * 128, src + j * 64);
            cp_commit();
        };

        load_stage(0, 0);

        // xg prefetch (fp16, 2 epilogue pairs per thread)
        float xg[2][4];
#pragma unroll
        for (int pp = 0; pp < 2; pp++) {
            const int p  = tid + pp * 256;
            const int bl = p >> 4, ui = p & 15;
            const __half* xgp = g_xg +
                (((size_t)t * NCG + cg) * BATCH + bg * MB + bl) * 64;
            xg[pp][0] = __half2float(xgp[ui]);
            xg[pp][1] = __half2float(xgp[16 + ui]);
            xg[pp][2] = __half2float(xgp[32 + ui]);
            xg[pp][3] = __half2float(xgp[48 + ui]);
        }

#pragma unroll
        for (int s = 0; s < 2; s++) {
            asm volatile("cp.async.wait_group 0;\n" ::: "memory");
            __syncthreads();
            if (s == 0) load_stage(1, 1);

            const uint32_t Ab = sA_u + s * A_STG + abase;
#pragma unroll
            for (int j = 0; j < 8; j++) {
                uint32_t a0[4], a1[4];
                LDSM4(a0, Ab + j * 32);
                LDSM4(a1, Ab + 16 * A_STRIDE + j * 32);
                const int k16g = s * 32 + kw * 8 + j;
#pragma unroll
                for (int ni = 0; ni < 4; ni++) {
                    const int n8g = nw * 4 + ni;
                    const uint32_t Bb = sW_u + (uint32_t)((k16g * 8 + n8g) * 256 + lane * 8);
                    uint32_t b0, b1;
                    LDSV2(b0, b1, Bb);
                    MMA_F16(acc[0][ni], a0, b0, b1);
                    MMA_F16(acc[1][ni], a1, b0, b1);
                }
            }
        }

        // K-partial store into padded smem [4][32][65] (overlay on A stage 0)
        {
            const int g = lane >> 2, t4 = lane & 3;
#pragma unroll
            for (int mi = 0; mi < 2; mi++)
#pragma unroll
                for (int ni = 0; ni < 4; ni++) {
                    const int r = mi * 16 + g;
                    const int c = (nw * 4 + ni) * 8 + t4 * 2;
                    float* p = sG4 + kw * SG_PLANE + r * 65 + c;
                    p[0]          = acc[mi][ni][0];
                    p[1]          = acc[mi][ni][1];
                    p[8 * 65]     = acc[mi][ni][2];
                    p[8 * 65 + 1] = acc[mi][ni][3];
                }
        }
        __syncthreads();

        // reduce 4 K-partials + cell update: 2 (batch,unit) pairs per thread
#pragma unroll
        for (int pp = 0; pp < 2; pp++) {
            const int p  = tid + pp * 256;
            const int bl = p >> 4, ui = p & 15;
            float gf = 0.f, gi = 0.f, gc_ = 0.f, go = 0.f;
#pragma unroll
            for (int k = 0; k < 4; k++) {
                const float* q = sG4 + k * SG_PLANE + bl * 65;
                gf  += q[ui];
                gi  += q[16 + ui];
                gc_ += q[32 + ui];
                go  += q[48 + ui];
            }
            float fg = sigmoidf_(gf  + xg[pp][0]);
            float ig = sigmoidf_(gi  + xg[pp][1]);
            float cg_ = tanhf   (gc_ + xg[pp][2]);
            float og = sigmoidf_(go  + xg[pp][3]);
            float& cst = pp ? cst1 : cst0;
            cst = fg * cst + ig * cg_;
            float h = og * tanhf(cst);
            const int b = bg * MB + bl;
            const int u = cg * UPC + ui;
            out[((size_t)b * SEQ + t) * HSZ + u] = h;
            g_h[wb][b * HSZ + u] = __float2half_rn(h);
            if (t == SEQ - 1 && write_final) {
                out[(size_t)BATCH * SEQ * HSZ + b * HSZ + u]               = h;
                out[(size_t)BATCH * SEQ * HSZ + BATCH * HSZ + b * HSZ + u] = cst;
            }
        }

        // flag-array grid barrier
        __syncthreads();
        if (tid == 0) {
            __threadfence();
            asm volatile("st.relaxed.gpu.u32 [%0], %1;"
                         :: "l"(g_flags + cb * 32), "r"((unsigned)(t + 1)) : "memory");
        }
        if (tid < NCTA) {
            const unsigned* fl = (const unsigned*)(g_flags + tid * 32);
            unsigned v;
            do {
                asm volatile("ld.acquire.gpu.u32 %0, [%1];" : "=r"(v) : "l"(fl) : "memory");
            } while (v < (unsigned)(t + 1));
        }
        __syncthreads();
    }
}

// ---------------- launch ----------------
extern "C" void kernel_launch(void* const* d_in, const int* in_sizes, int n_in,
                              void* d_out, int out_size) {
    const float* x = nullptr;
    const float* W = nullptr;
    const float* bias = nullptr;
    for (int i = 0; i < n_in; i++) {
        if (in_sizes[i] == BATCH * SEQ * ISZ)           x = (const float*)d_in[i];
        else if (in_sizes[i] == (ISZ + HSZ) * GSZ)      W = (const float*)d_in[i];
        else if (in_sizes[i] == GSZ)                    bias = (const float*)d_in[i];
    }
    float* out = (float*)d_out;
    const long long full = (long long)BATCH * SEQ * HSZ + 2LL * BATCH * HSZ;
    const int write_final = (out_size >= full) ? 1 : 0;

    cudaFuncSetAttribute(lstm_persist, cudaFuncAttributeMaxDynamicSharedMemorySize, SMEM_TOTAL);
    cudaFuncSetAttribute(xw_gemm, cudaFuncAttributeMaxDynamicSharedMemorySize, XG_SMEM);

    {
        int n4 = BATCH * SEQ * ISZ / 4;
        prep_x<<<(n4 + 255) / 256, 256>>>(x);
    }
    {
        long long n = (long long)NCG * WORDS_H;
        prep_wh<<<(unsigned)((n + 255) / 256), 256>>>(W);
    }
    {
        long long n = (long long)NCG * WORDS_X;
        prep_wx<<<(unsigned)((n + 255) / 256), 256>>>(W);
    }
    prep_state<<<(2 * BATCH * HSZ + 255) / 256, 256>>>();

    {
        dim3 grid(SEQ * BATCH / 128, NCG / CBQ);
        xw_gemm<<<grid, 256, XG_SMEM>>>(bias);
    }

    lstm_persist<<<NCTA, 256, SMEM_TOTAL>>>(out, write_final);
}